// round 10
// baseline (speedup 1.0000x reference)
#include <cuda_runtime.h>
#include <cuda_fp16.h>
#include <cstdint>

// =============================================================================
// MoE fused layer, plain sm_103. R10: R9 with the fp16 conversion split into
// cvtA (X, wg, wu — gates routed GU) and cvtB (wd + shared weights — hidden
// under routed GU on the second stream). GEMMs byte-identical to R8/R9.
// T=4096, D=1024, E=8, K=2, F=SF=1024.
// =============================================================================

#define NEXP   8
#define NTOK   4096
#define NROWS  8192
#define CPE    1024

// ---------------- device-global scratch --------------------------------------
__device__ __align__(16) __half g_hX  [4096u * 1024u];
__device__ __align__(16) __half g_hwg [8u * 1024u * 1024u];
__device__ __align__(16) __half g_hwu [8u * 1024u * 1024u];
__device__ __align__(16) __half g_hwd [8u * 1024u * 1024u];
__device__ __align__(16) __half g_hswg[1024u * 1024u];
__device__ __align__(16) __half g_hswu[1024u * 1024u];
__device__ __align__(16) __half g_hswd[1024u * 1024u];
__device__ __align__(16) __half g_H [8192u * 1024u];
__device__ __align__(16) __half g_SH[4096u * 1024u];
__device__ float g_Y [8192u * 1024u];
__device__ float g_S [4096u * 1024u];
__device__ int   g_perm[8192];
__device__ int   g_inv [8192];

// ---------------- helpers ------------------------------------------------------
__device__ __forceinline__ uint32_t smem_u32(const void* p) {
    uint32_t a;
    asm("{ .reg .u64 t; cvta.to.shared.u64 t, %1; cvt.u32.u64 %0, t; }"
        : "=r"(a) : "l"(p));
    return a;
}
__device__ __forceinline__ void cp_async16(uint32_t dst, const void* src) {
    asm volatile("cp.async.cg.shared.global [%0], [%1], 16;"
                 :: "r"(dst), "l"(src) : "memory");
}
__device__ __forceinline__ void cp_commit() {
    asm volatile("cp.async.commit_group;" ::: "memory");
}
template<int N>
__device__ __forceinline__ void cp_wait() {
    asm volatile("cp.async.wait_group %0;" :: "n"(N) : "memory");
}
__device__ __forceinline__ void ldsm_x4(uint32_t* r, uint32_t addr) {
    asm volatile("ldmatrix.sync.aligned.m8n8.x4.shared.b16 {%0,%1,%2,%3}, [%4];"
                 : "=r"(r[0]), "=r"(r[1]), "=r"(r[2]), "=r"(r[3]) : "r"(addr));
}
__device__ __forceinline__ void ldsm_x4t(uint32_t* r, uint32_t addr) {
    asm volatile("ldmatrix.sync.aligned.m8n8.x4.trans.shared.b16 {%0,%1,%2,%3}, [%4];"
                 : "=r"(r[0]), "=r"(r[1]), "=r"(r[2]), "=r"(r[3]) : "r"(addr));
}
__device__ __forceinline__ void mma_f16(float* d, const uint32_t* a,
                                        const uint32_t* b) {
    asm volatile(
        "mma.sync.aligned.m16n8k16.row.col.f32.f16.f16.f32 "
        "{%0,%1,%2,%3}, {%4,%5,%6,%7}, {%8,%9}, {%0,%1,%2,%3};"
        : "+f"(d[0]), "+f"(d[1]), "+f"(d[2]), "+f"(d[3])
        : "r"(a[0]), "r"(a[1]), "r"(a[2]), "r"(a[3]), "r"(b[0]), "r"(b[1]));
}
__device__ __forceinline__ float silu(float x) {
    return x / (1.f + __expf(-x));
}

// =============================================================================
// fp32 -> fp16 conversion, split in two phases.
// cvtA: X (1048576 f4) | wg (2097152) | wu (2097152)           = 5242880
// cvtB: wd (2097152) | swg (262144) | swu (262144) | swd (262144) = 2883584
// =============================================================================
__global__ void __launch_bounds__(256) cvt_A(
    const float* __restrict__ x,
    const float* __restrict__ wg, const float* __restrict__ wu)
{
    const size_t total = 5242880u;
    for (size_t i = (size_t)blockIdx.x * blockDim.x + threadIdx.x;
         i < total; i += (size_t)gridDim.x * blockDim.x) {
        const float4* s; __half2* d; size_t j;
        if      (i < 1048576u) { s = (const float4*)x;  d = (__half2*)g_hX;  j = i; }
        else if (i < 3145728u) { s = (const float4*)wg; d = (__half2*)g_hwg; j = i - 1048576u; }
        else                   { s = (const float4*)wu; d = (__half2*)g_hwu; j = i - 3145728u; }
        const float4 v = s[j];
        d[2 * j]     = __floats2half2_rn(v.x, v.y);
        d[2 * j + 1] = __floats2half2_rn(v.z, v.w);
    }
}

__global__ void __launch_bounds__(256) cvt_B(
    const float* __restrict__ wd,
    const float* __restrict__ swg, const float* __restrict__ swu,
    const float* __restrict__ swd)
{
    const size_t total = 2883584u;
    for (size_t i = (size_t)blockIdx.x * blockDim.x + threadIdx.x;
         i < total; i += (size_t)gridDim.x * blockDim.x) {
        const float4* s; __half2* d; size_t j;
        if      (i < 2097152u) { s = (const float4*)wd;  d = (__half2*)g_hwd;  j = i; }
        else if (i < 2359296u) { s = (const float4*)swg; d = (__half2*)g_hswg; j = i - 2097152u; }
        else if (i < 2621440u) { s = (const float4*)swu; d = (__half2*)g_hswu; j = i - 2359296u; }
        else                   { s = (const float4*)swd; d = (__half2*)g_hswd; j = i - 2621440u; }
        const float4 v = s[j];
        d[2 * j]     = __floats2half2_rn(v.x, v.y);
        d[2 * j + 1] = __floats2half2_rn(v.z, v.w);
    }
}

// =============================================================================
// Stable counting-sort permutation via warp ballots.
// =============================================================================
__global__ void build_perm_kernel(const int* __restrict__ tki) {
    const int e    = blockIdx.x;
    const int tid  = threadIdx.x;
    const int lane = tid & 31;
    const int w    = tid >> 5;
    __shared__ int wcnt[8];
    __shared__ int basev;
    if (tid == 0) basev = 0;
    __syncthreads();
    for (int start = 0; start < NROWS; start += 256) {
        const int i = start + tid;
        const bool m = (tki[i] == e);
        const uint32_t mask = __ballot_sync(0xffffffffu, m);
        if (lane == 0) wcnt[w] = __popc(mask);
        __syncthreads();
        int wpre = 0, tot = 0;
        #pragma unroll
        for (int ww = 0; ww < 8; ++ww) {
            const int c = wcnt[ww];
            wpre += (ww < w) ? c : 0;
            tot  += c;
        }
        if (m) {
            const int rank = __popc(mask & ((1u << lane) - 1u));
            const int dest = e * CPE + basev + wpre + rank;
            g_perm[dest] = i;
            g_inv[i] = dest;
        }
        __syncthreads();
        if (tid == 0) basev += tot;
        __syncthreads();
    }
}

// =============================================================================
// Fused gate+up GEMM (R8 verbatim — known good).
// =============================================================================
#define GU_STG   36864
#define GU_SMEM  (3 * GU_STG + 512)

template<bool GATHER>
__global__ void __launch_bounds__(256, 2) gemm_gu(
    const __half* __restrict__ A,
    const __half* __restrict__ B0g,
    const __half* __restrict__ B1g,
    __half* __restrict__ Out)
{
    extern __shared__ char sm[];
    const uint32_t smem = smem_u32(sm);
    int* srcRow = (int*)(sm + 3 * GU_STG);

    const int tid  = threadIdx.x;
    const int wid  = tid >> 5;
    const int lane = tid & 31;
    const int row4 = lane >> 2;
    const int kq   = lane & 3;
    const int rl   = lane & 7;
    const int sel  = lane >> 3;
    const int mat  = wid >> 2;
    const int wm   = (wid >> 1) & 1;
    const int wn2  = wid & 1;

    const int mBase = (blockIdx.z * gridDim.x + blockIdx.x) * 128;
    const int nBase = blockIdx.y * 64;

    if (tid < 128)
        srcRow[tid] = GATHER ? (g_perm[mBase + tid] >> 1) : (mBase + tid);
    __syncthreads();

    const __half* B0 = B0g + (size_t)blockIdx.z * 1048576u;
    const __half* B1 = B1g + (size_t)blockIdx.z * 1048576u;

    const __half* aSrc[4]; uint32_t aDst[4];
    const __half* bSrc[4]; uint32_t bDst[4];
    #pragma unroll
    for (int it = 0; it < 4; ++it) {
        const int ia = tid + it * 256;
        const int r = ia >> 3, q = ia & 7;
        aSrc[it] = A + (size_t)srcRow[r] * 1024 + q * 8;
        aDst[it] = smem + r * 144 + q * 16;
        const int mm = ia >> 9, kr = (ia >> 3) & 63, qb = ia & 7;
        bSrc[it] = (mm ? B1 : B0) + (size_t)kr * 1024 + nBase + qb * 8;
        bDst[it] = smem + 18432 + mm * 9216 + kr * 144 + qb * 16;
    }

    const uint32_t aBase = smem + (wm * 64 + (sel & 1) * 8 + rl) * 144
                         + (sel >> 1) * 16;
    const uint32_t bBase = smem + 18432 + mat * 9216
                         + ((sel & 1) * 8 + rl) * 144
                         + (wn2 * 32 + (sel >> 1) * 8) * 2;

    float d[4][4][4];
    #pragma unroll
    for (int f = 0; f < 4; ++f)
        #pragma unroll
        for (int g = 0; g < 4; ++g)
            #pragma unroll
            for (int j = 0; j < 4; ++j) d[f][g][j] = 0.f;

    auto issue = [&](int ch, uint32_t soff) {
        const int k0 = ch * 64;
        #pragma unroll
        for (int it = 0; it < 4; ++it)
            cp_async16(aDst[it] + soff, aSrc[it] + k0);
        #pragma unroll
        for (int it = 0; it < 4; ++it)
            cp_async16(bDst[it] + soff, bSrc[it] + (size_t)k0 * 1024);
        cp_commit();
    };

    issue(0, 0);
    issue(1, GU_STG);

    uint32_t cs = 0, ns = 2 * GU_STG;
    for (int ch = 0; ch < 16; ++ch) {
        if (ch < 15) cp_wait<1>(); else cp_wait<0>();
        __syncthreads();
        if (ch < 14) {
            issue(ch + 2, ns);
            ns = (ns == 2 * GU_STG) ? 0 : ns + GU_STG;
        }
        #pragma unroll
        for (int ks = 0; ks < 4; ++ks) {
            uint32_t af[4][4];
            #pragma unroll
            for (int f = 0; f < 4; ++f)
                ldsm_x4(af[f], aBase + cs + f * 2304 + ks * 32);
            uint32_t bf[2][4];
            #pragma unroll
            for (int g2 = 0; g2 < 2; ++g2)
                ldsm_x4t(bf[g2], bBase + cs + ks * 2304 + g2 * 32);
            #pragma unroll
            for (int f = 0; f < 4; ++f)
                #pragma unroll
                for (int g = 0; g < 4; ++g)
                    mma_f16(d[f][g], af[f], &bf[g >> 1][(g & 1) * 2]);
        }
        cs = (cs == 2 * GU_STG) ? 0 : cs + GU_STG;
    }

    __syncthreads();
    float* Us = (float*)sm;             // [128][66]
    if (mat == 1) {
        #pragma unroll
        for (int f = 0; f < 4; ++f) {
            const int r = wm * 64 + f * 16 + row4;
            #pragma unroll
            for (int g = 0; g < 4; ++g) {
                const int c = wn2 * 32 + g * 8 + kq * 2;
                *(float2*)(Us + r * 66 + c)       = make_float2(d[f][g][0], d[f][g][1]);
                *(float2*)(Us + (r + 8) * 66 + c) = make_float2(d[f][g][2], d[f][g][3]);
            }
        }
    }
    __syncthreads();
    if (mat == 0) {
        #pragma unroll
        for (int f = 0; f < 4; ++f) {
            const int r = wm * 64 + f * 16 + row4;
            #pragma unroll
            for (int g = 0; g < 4; ++g) {
                const int c = wn2 * 32 + g * 8 + kq * 2;
                const float2 u0 = *(const float2*)(Us + r * 66 + c);
                const float2 u1 = *(const float2*)(Us + (r + 8) * 66 + c);
                *(__half2*)(Out + (size_t)(mBase + r) * 1024 + nBase + c) =
                    __floats2half2_rn(silu(d[f][g][0]) * u0.x,
                                      silu(d[f][g][1]) * u0.y);
                *(__half2*)(Out + (size_t)(mBase + r + 8) * 1024 + nBase + c) =
                    __floats2half2_rn(silu(d[f][g][2]) * u1.x,
                                      silu(d[f][g][3]) * u1.y);
            }
        }
    }
}

// =============================================================================
// Down GEMM (R8 verbatim — known good).
// =============================================================================
#define DN_STG   35840
#define DN_SMEM  (3 * DN_STG + 256)

__global__ void __launch_bounds__(256, 2) gemm_dn(
    const __half* __restrict__ A,
    const __half* __restrict__ Bg,
    float* __restrict__ Out)
{
    extern __shared__ char sm[];
    const uint32_t smem = smem_u32(sm);

    const int tid  = threadIdx.x;
    const int wid  = tid >> 5;
    const int lane = tid & 31;
    const int row4 = lane >> 2;
    const int kq   = lane & 3;
    const int rl   = lane & 7;
    const int sel  = lane >> 3;
    const int wm   = wid & 1;
    const int nOff = (wid >> 1) * 32;

    const int mBase = (blockIdx.z * gridDim.x + blockIdx.x) * 128;
    const int nBase = blockIdx.y * 128;

    const __half* B = Bg + (size_t)blockIdx.z * (1024u * 1024u);

    const __half* aSrc[4]; uint32_t aDst[4];
    const __half* bSrc[4]; uint32_t bDst[4];
    #pragma unroll
    for (int it = 0; it < 4; ++it) {
        const int ia = tid + it * 256;
        const int r = ia >> 3, q = ia & 7;
        aSrc[it] = A + (size_t)(mBase + r) * 1024 + q * 8;
        aDst[it] = smem + r * 144 + q * 16;
        const int kr = ia >> 4, qb = ia & 15;
        bSrc[it] = B + (size_t)kr * 1024 + nBase + qb * 8;
        bDst[it] = smem + 18432 + kr * 272 + qb * 16;
    }

    const uint32_t aBase = smem + (wm * 64 + (sel & 1) * 8 + rl) * 144
                         + (sel >> 1) * 16;
    const uint32_t bBase = smem + 18432 + ((sel & 1) * 8 + rl) * 272
                         + (nOff + (sel >> 1) * 8) * 2;

    float d[4][4][4];
    #pragma unroll
    for (int f = 0; f < 4; ++f)
        #pragma unroll
        for (int g = 0; g < 4; ++g)
            #pragma unroll
            for (int j = 0; j < 4; ++j) d[f][g][j] = 0.f;

    auto issue = [&](int ch, uint32_t soff) {
        const int k0 = ch * 64;
        #pragma unroll
        for (int it = 0; it < 4; ++it)
            cp_async16(aDst[it] + soff, aSrc[it] + k0);
        #pragma unroll
        for (int it = 0; it < 4; ++it)
            cp_async16(bDst[it] + soff, bSrc[it] + (size_t)k0 * 1024);
        cp_commit();
    };

    issue(0, 0);
    issue(1, DN_STG);

    uint32_t cs = 0, ns = 2 * DN_STG;
    for (int ch = 0; ch < 16; ++ch) {
        if (ch < 15) cp_wait<1>(); else cp_wait<0>();
        __syncthreads();
        if (ch < 14) {
            issue(ch + 2, ns);
            ns = (ns == 2 * DN_STG) ? 0 : ns + DN_STG;
        }
        #pragma unroll
        for (int ks = 0; ks < 4; ++ks) {
            uint32_t af[4][4];
            #pragma unroll
            for (int f = 0; f < 4; ++f)
                ldsm_x4(af[f], aBase + cs + f * 2304 + ks * 32);
            uint32_t bf[2][4];
            #pragma unroll
            for (int g2 = 0; g2 < 2; ++g2)
                ldsm_x4t(bf[g2], bBase + cs + ks * 4352 + g2 * 32);
            #pragma unroll
            for (int f = 0; f < 4; ++f)
                #pragma unroll
                for (int g = 0; g < 4; ++g)
                    mma_f16(d[f][g], af[f], &bf[g >> 1][(g & 1) * 2]);
        }
        cs = (cs == 2 * DN_STG) ? 0 : cs + DN_STG;
    }

    #pragma unroll
    for (int f = 0; f < 4; ++f) {
        const int r = mBase + wm * 64 + f * 16 + row4;
        #pragma unroll
        for (int g = 0; g < 4; ++g) {
            const int c = nBase + nOff + g * 8 + kq * 2;
            *(float2*)(Out + (size_t)r * 1024 + c) =
                make_float2(d[f][g][0], d[f][g][1]);
            *(float2*)(Out + (size_t)(r + 8) * 1024 + c) =
                make_float2(d[f][g][2], d[f][g][3]);
        }
    }
}

// =============================================================================
// Final combine (shuffle reduction).
// =============================================================================
__global__ void __launch_bounds__(256) combine_kernel(
    const float* __restrict__ X, const float* __restrict__ tw,
    const float* __restrict__ gw, float* __restrict__ out)
{
    const int t = blockIdx.x;
    const int tid = threadIdx.x;
    const int lane = tid & 31, w = tid >> 5;
    __shared__ float wsum[8];

    const float4 xv = ((const float4*)(X + (size_t)t * 1024))[tid];
    const float4 gv = ((const float4*)gw)[tid];
    float acc = xv.x * gv.x + xv.y * gv.y + xv.z * gv.z + xv.w * gv.w;
    #pragma unroll
    for (int o = 16; o; o >>= 1)
        acc += __shfl_xor_sync(0xffffffffu, acc, o);
    if (lane == 0) wsum[w] = acc;
    __syncthreads();
    float tot = 0.f;
    #pragma unroll
    for (int ww = 0; ww < 8; ++ww) tot += wsum[ww];

    const float g = 1.f / (1.f + __expf(-tot));
    const int r0 = g_inv[2 * t], r1 = g_inv[2 * t + 1];
    const float w0 = tw[2 * t], w1 = tw[2 * t + 1];
    const float4 a = ((const float4*)(g_Y + (size_t)r0 * 1024))[tid];
    const float4 b = ((const float4*)(g_Y + (size_t)r1 * 1024))[tid];
    const float4 c = ((const float4*)(g_S + (size_t)t  * 1024))[tid];
    float4 r;
    r.x = w0 * a.x + w1 * b.x + g * c.x;
    r.y = w0 * a.y + w1 * b.y + g * c.y;
    r.z = w0 * a.z + w1 * b.z + g * c.z;
    r.w = w0 * a.w + w1 * b.w + g * c.w;
    ((float4*)(out + (size_t)t * 1024))[tid] = r;
}

// =============================================================================
extern "C" void kernel_launch(void* const* d_in, const int* in_sizes, int n_in,
                              void* d_out, int out_size) {
    (void)in_sizes; (void)n_in; (void)out_size;
    const float* X   = (const float*)d_in[0];
    const float* tw  = (const float*)d_in[1];
    const float* wg  = (const float*)d_in[2];
    const float* wu  = (const float*)d_in[3];
    const float* wd  = (const float*)d_in[4];
    const float* swg = (const float*)d_in[5];
    const float* swu = (const float*)d_in[6];
    const float* swd = (const float*)d_in[7];
    const float* gw  = (const float*)d_in[8];
    const int*   tki = (const int*)d_in[9];
    float* out = (float*)d_out;

    __half *hX, *hWg, *hWu, *hWd, *hSg, *hSu, *hSd, *H, *SH;
    float *Y, *S;
    cudaGetSymbolAddress((void**)&hX,  g_hX);
    cudaGetSymbolAddress((void**)&hWg, g_hwg);
    cudaGetSymbolAddress((void**)&hWu, g_hwu);
    cudaGetSymbolAddress((void**)&hWd, g_hwd);
    cudaGetSymbolAddress((void**)&hSg, g_hswg);
    cudaGetSymbolAddress((void**)&hSu, g_hswu);
    cudaGetSymbolAddress((void**)&hSd, g_hswd);
    cudaGetSymbolAddress((void**)&H,   g_H);
    cudaGetSymbolAddress((void**)&SH,  g_SH);
    cudaGetSymbolAddress((void**)&Y,   g_Y);
    cudaGetSymbolAddress((void**)&S,   g_S);

    // one-time (uncaptured first call) stream/event creation — no device allocs
    static cudaStream_t s1 = nullptr;
    static cudaEvent_t evStart = nullptr, evCvtA = nullptr, evCvtB = nullptr,
                       evPerm = nullptr, evShared = nullptr;
    if (!s1) {
        cudaStreamCreateWithFlags(&s1, cudaStreamNonBlocking);
        cudaEventCreateWithFlags(&evStart,  cudaEventDisableTiming);
        cudaEventCreateWithFlags(&evCvtA,   cudaEventDisableTiming);
        cudaEventCreateWithFlags(&evCvtB,   cudaEventDisableTiming);
        cudaEventCreateWithFlags(&evPerm,   cudaEventDisableTiming);
        cudaEventCreateWithFlags(&evShared, cudaEventDisableTiming);
        cudaFuncSetAttribute(gemm_gu<true >, cudaFuncAttributeMaxDynamicSharedMemorySize, GU_SMEM);
        cudaFuncSetAttribute(gemm_gu<false>, cudaFuncAttributeMaxDynamicSharedMemorySize, GU_SMEM);
        cudaFuncSetAttribute(gemm_dn,        cudaFuncAttributeMaxDynamicSharedMemorySize, DN_SMEM);
    }

    // ---- stream 0: cvtA (X, wg, wu) ------------------------------------------
    cudaEventRecord(evStart, 0);
    cvt_A<<<2368, 256>>>(X, wg, wu);
    cudaEventRecord(evCvtA, 0);

    // ---- stream s1: perm (|| cvtA), cvtB, then shared chain -------------------
    cudaStreamWaitEvent(s1, evStart, 0);
    build_perm_kernel<<<NEXP, 256, 0, s1>>>(tki);
    cudaEventRecord(evPerm, s1);
    cvt_B<<<1536, 256, 0, s1>>>(wd, swg, swu, swd);
    cudaEventRecord(evCvtB, s1);
    cudaStreamWaitEvent(s1, evCvtA, 0);
    gemm_gu<false><<<dim3(32, 16, 1), 256, GU_SMEM, s1>>>(hX, hSg, hSu, SH);
    gemm_dn<<<dim3(32, 8, 1), 256, DN_SMEM, s1>>>(SH, hSd, S);
    cudaEventRecord(evShared, s1);

    // ---- stream 0: routed chain, then join + combine -------------------------
    cudaStreamWaitEvent(0, evPerm, 0);
    gemm_gu<true ><<<dim3(8, 16, NEXP), 256, GU_SMEM>>>(hX, hWg, hWu, H);
    cudaStreamWaitEvent(0, evCvtB, 0);
    gemm_dn<<<dim3(8, 8, NEXP), 256, DN_SMEM>>>(H, hWd, Y);
    cudaStreamWaitEvent(0, evShared, 0);
    combine_kernel<<<NTOK, 256>>>(X, tw, gw, out);
}

// round 11
// speedup vs baseline: 1.0078x; 1.0078x over previous
#include <cuda_runtime.h>
#include <cuda_fp16.h>
#include <cstdint>

// =============================================================================
// MoE fused layer, plain sm_103. R11: R9 schedule (single cvt, fork-join
// streams), GEMM mainloops unchanged (at legacy-HMMA throughput ceiling),
// Y/S intermediates now fp16 to cut DN-store + combine-load DRAM traffic.
// T=4096, D=1024, E=8, K=2, F=SF=1024.
// =============================================================================

#define NEXP   8
#define NTOK   4096
#define NROWS  8192
#define CPE    1024

// ---------------- device-global scratch --------------------------------------
__device__ __align__(16) __half g_hX  [4096u * 1024u];
__device__ __align__(16) __half g_hwg [8u * 1024u * 1024u];
__device__ __align__(16) __half g_hwu [8u * 1024u * 1024u];
__device__ __align__(16) __half g_hwd [8u * 1024u * 1024u];
__device__ __align__(16) __half g_hswg[1024u * 1024u];
__device__ __align__(16) __half g_hswu[1024u * 1024u];
__device__ __align__(16) __half g_hswd[1024u * 1024u];
__device__ __align__(16) __half g_H [8192u * 1024u];   // routed hidden
__device__ __align__(16) __half g_SH[4096u * 1024u];   // shared hidden
__device__ __align__(16) __half g_Y [8192u * 1024u];   // routed down out (fp16)
__device__ __align__(16) __half g_S [4096u * 1024u];   // shared down out (fp16)
__device__ int   g_perm[8192];
__device__ int   g_inv [8192];

// ---------------- helpers ------------------------------------------------------
__device__ __forceinline__ uint32_t smem_u32(const void* p) {
    uint32_t a;
    asm("{ .reg .u64 t; cvta.to.shared.u64 t, %1; cvt.u32.u64 %0, t; }"
        : "=r"(a) : "l"(p));
    return a;
}
__device__ __forceinline__ void cp_async16(uint32_t dst, const void* src) {
    asm volatile("cp.async.cg.shared.global [%0], [%1], 16;"
                 :: "r"(dst), "l"(src) : "memory");
}
__device__ __forceinline__ void cp_commit() {
    asm volatile("cp.async.commit_group;" ::: "memory");
}
template<int N>
__device__ __forceinline__ void cp_wait() {
    asm volatile("cp.async.wait_group %0;" :: "n"(N) : "memory");
}
__device__ __forceinline__ void ldsm_x4(uint32_t* r, uint32_t addr) {
    asm volatile("ldmatrix.sync.aligned.m8n8.x4.shared.b16 {%0,%1,%2,%3}, [%4];"
                 : "=r"(r[0]), "=r"(r[1]), "=r"(r[2]), "=r"(r[3]) : "r"(addr));
}
__device__ __forceinline__ void ldsm_x4t(uint32_t* r, uint32_t addr) {
    asm volatile("ldmatrix.sync.aligned.m8n8.x4.trans.shared.b16 {%0,%1,%2,%3}, [%4];"
                 : "=r"(r[0]), "=r"(r[1]), "=r"(r[2]), "=r"(r[3]) : "r"(addr));
}
__device__ __forceinline__ void mma_f16(float* d, const uint32_t* a,
                                        const uint32_t* b) {
    asm volatile(
        "mma.sync.aligned.m16n8k16.row.col.f32.f16.f16.f32 "
        "{%0,%1,%2,%3}, {%4,%5,%6,%7}, {%8,%9}, {%0,%1,%2,%3};"
        : "+f"(d[0]), "+f"(d[1]), "+f"(d[2]), "+f"(d[3])
        : "r"(a[0]), "r"(a[1]), "r"(a[2]), "r"(a[3]), "r"(b[0]), "r"(b[1]));
}
__device__ __forceinline__ float silu(float x) {
    return x / (1.f + __expf(-x));
}

// =============================================================================
// fp32 -> fp16 conversion of all MMA inputs (single pass, R9 schedule).
// =============================================================================
__global__ void __launch_bounds__(256) cvt_all(
    const float* __restrict__ x,
    const float* __restrict__ wg,  const float* __restrict__ wu,
    const float* __restrict__ wd,
    const float* __restrict__ swg, const float* __restrict__ swu,
    const float* __restrict__ swd)
{
    const size_t total = 8126464u;   // float4 units
    for (size_t i = (size_t)blockIdx.x * blockDim.x + threadIdx.x;
         i < total; i += (size_t)gridDim.x * blockDim.x) {
        const float4* s; __half2* d; size_t j;
        if      (i < 1048576u) { s = (const float4*)x;   d = (__half2*)g_hX;   j = i; }
        else if (i < 3145728u) { s = (const float4*)wg;  d = (__half2*)g_hwg;  j = i - 1048576u; }
        else if (i < 5242880u) { s = (const float4*)wu;  d = (__half2*)g_hwu;  j = i - 3145728u; }
        else if (i < 7340032u) { s = (const float4*)wd;  d = (__half2*)g_hwd;  j = i - 5242880u; }
        else if (i < 7602176u) { s = (const float4*)swg; d = (__half2*)g_hswg; j = i - 7340032u; }
        else if (i < 7864320u) { s = (const float4*)swu; d = (__half2*)g_hswu; j = i - 7602176u; }
        else                   { s = (const float4*)swd; d = (__half2*)g_hswd; j = i - 7864320u; }
        const float4 v = s[j];
        d[2 * j]     = __floats2half2_rn(v.x, v.y);
        d[2 * j + 1] = __floats2half2_rn(v.z, v.w);
    }
}

// =============================================================================
// Stable counting-sort permutation via warp ballots.
// =============================================================================
__global__ void build_perm_kernel(const int* __restrict__ tki) {
    const int e    = blockIdx.x;
    const int tid  = threadIdx.x;
    const int lane = tid & 31;
    const int w    = tid >> 5;
    __shared__ int wcnt[8];
    __shared__ int basev;
    if (tid == 0) basev = 0;
    __syncthreads();
    for (int start = 0; start < NROWS; start += 256) {
        const int i = start + tid;
        const bool m = (tki[i] == e);
        const uint32_t mask = __ballot_sync(0xffffffffu, m);
        if (lane == 0) wcnt[w] = __popc(mask);
        __syncthreads();
        int wpre = 0, tot = 0;
        #pragma unroll
        for (int ww = 0; ww < 8; ++ww) {
            const int c = wcnt[ww];
            wpre += (ww < w) ? c : 0;
            tot  += c;
        }
        if (m) {
            const int rank = __popc(mask & ((1u << lane) - 1u));
            const int dest = e * CPE + basev + wpre + rank;
            g_perm[dest] = i;
            g_inv[i] = dest;
        }
        __syncthreads();
        if (tid == 0) basev += tot;
        __syncthreads();
    }
}

// =============================================================================
// Fused gate+up GEMM (R8 verbatim — known good, ceiling-bound).
// =============================================================================
#define GU_STG   36864
#define GU_SMEM  (3 * GU_STG + 512)

template<bool GATHER>
__global__ void __launch_bounds__(256, 2) gemm_gu(
    const __half* __restrict__ A,
    const __half* __restrict__ B0g,
    const __half* __restrict__ B1g,
    __half* __restrict__ Out)
{
    extern __shared__ char sm[];
    const uint32_t smem = smem_u32(sm);
    int* srcRow = (int*)(sm + 3 * GU_STG);

    const int tid  = threadIdx.x;
    const int wid  = tid >> 5;
    const int lane = tid & 31;
    const int row4 = lane >> 2;
    const int kq   = lane & 3;
    const int rl   = lane & 7;
    const int sel  = lane >> 3;
    const int mat  = wid >> 2;
    const int wm   = (wid >> 1) & 1;
    const int wn2  = wid & 1;

    const int mBase = (blockIdx.z * gridDim.x + blockIdx.x) * 128;
    const int nBase = blockIdx.y * 64;

    if (tid < 128)
        srcRow[tid] = GATHER ? (g_perm[mBase + tid] >> 1) : (mBase + tid);
    __syncthreads();

    const __half* B0 = B0g + (size_t)blockIdx.z * 1048576u;
    const __half* B1 = B1g + (size_t)blockIdx.z * 1048576u;

    const __half* aSrc[4]; uint32_t aDst[4];
    const __half* bSrc[4]; uint32_t bDst[4];
    #pragma unroll
    for (int it = 0; it < 4; ++it) {
        const int ia = tid + it * 256;
        const int r = ia >> 3, q = ia & 7;
        aSrc[it] = A + (size_t)srcRow[r] * 1024 + q * 8;
        aDst[it] = smem + r * 144 + q * 16;
        const int mm = ia >> 9, kr = (ia >> 3) & 63, qb = ia & 7;
        bSrc[it] = (mm ? B1 : B0) + (size_t)kr * 1024 + nBase + qb * 8;
        bDst[it] = smem + 18432 + mm * 9216 + kr * 144 + qb * 16;
    }

    const uint32_t aBase = smem + (wm * 64 + (sel & 1) * 8 + rl) * 144
                         + (sel >> 1) * 16;
    const uint32_t bBase = smem + 18432 + mat * 9216
                         + ((sel & 1) * 8 + rl) * 144
                         + (wn2 * 32 + (sel >> 1) * 8) * 2;

    float d[4][4][4];
    #pragma unroll
    for (int f = 0; f < 4; ++f)
        #pragma unroll
        for (int g = 0; g < 4; ++g)
            #pragma unroll
            for (int j = 0; j < 4; ++j) d[f][g][j] = 0.f;

    auto issue = [&](int ch, uint32_t soff) {
        const int k0 = ch * 64;
        #pragma unroll
        for (int it = 0; it < 4; ++it)
            cp_async16(aDst[it] + soff, aSrc[it] + k0);
        #pragma unroll
        for (int it = 0; it < 4; ++it)
            cp_async16(bDst[it] + soff, bSrc[it] + (size_t)k0 * 1024);
        cp_commit();
    };

    issue(0, 0);
    issue(1, GU_STG);

    uint32_t cs = 0, ns = 2 * GU_STG;
    for (int ch = 0; ch < 16; ++ch) {
        if (ch < 15) cp_wait<1>(); else cp_wait<0>();
        __syncthreads();
        if (ch < 14) {
            issue(ch + 2, ns);
            ns = (ns == 2 * GU_STG) ? 0 : ns + GU_STG;
        }
        #pragma unroll
        for (int ks = 0; ks < 4; ++ks) {
            uint32_t af[4][4];
            #pragma unroll
            for (int f = 0; f < 4; ++f)
                ldsm_x4(af[f], aBase + cs + f * 2304 + ks * 32);
            uint32_t bf[2][4];
            #pragma unroll
            for (int g2 = 0; g2 < 2; ++g2)
                ldsm_x4t(bf[g2], bBase + cs + ks * 2304 + g2 * 32);
            #pragma unroll
            for (int f = 0; f < 4; ++f)
                #pragma unroll
                for (int g = 0; g < 4; ++g)
                    mma_f16(d[f][g], af[f], &bf[g >> 1][(g & 1) * 2]);
        }
        cs = (cs == 2 * GU_STG) ? 0 : cs + GU_STG;
    }

    __syncthreads();
    float* Us = (float*)sm;             // [128][66]
    if (mat == 1) {
        #pragma unroll
        for (int f = 0; f < 4; ++f) {
            const int r = wm * 64 + f * 16 + row4;
            #pragma unroll
            for (int g = 0; g < 4; ++g) {
                const int c = wn2 * 32 + g * 8 + kq * 2;
                *(float2*)(Us + r * 66 + c)       = make_float2(d[f][g][0], d[f][g][1]);
                *(float2*)(Us + (r + 8) * 66 + c) = make_float2(d[f][g][2], d[f][g][3]);
            }
        }
    }
    __syncthreads();
    if (mat == 0) {
        #pragma unroll
        for (int f = 0; f < 4; ++f) {
            const int r = wm * 64 + f * 16 + row4;
            #pragma unroll
            for (int g = 0; g < 4; ++g) {
                const int c = wn2 * 32 + g * 8 + kq * 2;
                const float2 u0 = *(const float2*)(Us + r * 66 + c);
                const float2 u1 = *(const float2*)(Us + (r + 8) * 66 + c);
                *(__half2*)(Out + (size_t)(mBase + r) * 1024 + nBase + c) =
                    __floats2half2_rn(silu(d[f][g][0]) * u0.x,
                                      silu(d[f][g][1]) * u0.y);
                *(__half2*)(Out + (size_t)(mBase + r + 8) * 1024 + nBase + c) =
                    __floats2half2_rn(silu(d[f][g][2]) * u1.x,
                                      silu(d[f][g][3]) * u1.y);
            }
        }
    }
}

// =============================================================================
// Down GEMM (R8 mainloop verbatim; epilogue now stores fp16).
// =============================================================================
#define DN_STG   35840
#define DN_SMEM  (3 * DN_STG + 256)

__global__ void __launch_bounds__(256, 2) gemm_dn(
    const __half* __restrict__ A,
    const __half* __restrict__ Bg,
    __half* __restrict__ Out)
{
    extern __shared__ char sm[];
    const uint32_t smem = smem_u32(sm);

    const int tid  = threadIdx.x;
    const int wid  = tid >> 5;
    const int lane = tid & 31;
    const int row4 = lane >> 2;
    const int kq   = lane & 3;
    const int rl   = lane & 7;
    const int sel  = lane >> 3;
    const int wm   = wid & 1;
    const int nOff = (wid >> 1) * 32;

    const int mBase = (blockIdx.z * gridDim.x + blockIdx.x) * 128;
    const int nBase = blockIdx.y * 128;

    const __half* B = Bg + (size_t)blockIdx.z * (1024u * 1024u);

    const __half* aSrc[4]; uint32_t aDst[4];
    const __half* bSrc[4]; uint32_t bDst[4];
    #pragma unroll
    for (int it = 0; it < 4; ++it) {
        const int ia = tid + it * 256;
        const int r = ia >> 3, q = ia & 7;
        aSrc[it] = A + (size_t)(mBase + r) * 1024 + q * 8;
        aDst[it] = smem + r * 144 + q * 16;
        const int kr = ia >> 4, qb = ia & 15;
        bSrc[it] = B + (size_t)kr * 1024 + nBase + qb * 8;
        bDst[it] = smem + 18432 + kr * 272 + qb * 16;
    }

    const uint32_t aBase = smem + (wm * 64 + (sel & 1) * 8 + rl) * 144
                         + (sel >> 1) * 16;
    const uint32_t bBase = smem + 18432 + ((sel & 1) * 8 + rl) * 272
                         + (nOff + (sel >> 1) * 8) * 2;

    float d[4][4][4];
    #pragma unroll
    for (int f = 0; f < 4; ++f)
        #pragma unroll
        for (int g = 0; g < 4; ++g)
            #pragma unroll
            for (int j = 0; j < 4; ++j) d[f][g][j] = 0.f;

    auto issue = [&](int ch, uint32_t soff) {
        const int k0 = ch * 64;
        #pragma unroll
        for (int it = 0; it < 4; ++it)
            cp_async16(aDst[it] + soff, aSrc[it] + k0);
        #pragma unroll
        for (int it = 0; it < 4; ++it)
            cp_async16(bDst[it] + soff, bSrc[it] + (size_t)k0 * 1024);
        cp_commit();
    };

    issue(0, 0);
    issue(1, DN_STG);

    uint32_t cs = 0, ns = 2 * DN_STG;
    for (int ch = 0; ch < 16; ++ch) {
        if (ch < 15) cp_wait<1>(); else cp_wait<0>();
        __syncthreads();
        if (ch < 14) {
            issue(ch + 2, ns);
            ns = (ns == 2 * DN_STG) ? 0 : ns + DN_STG;
        }
        #pragma unroll
        for (int ks = 0; ks < 4; ++ks) {
            uint32_t af[4][4];
            #pragma unroll
            for (int f = 0; f < 4; ++f)
                ldsm_x4(af[f], aBase + cs + f * 2304 + ks * 32);
            uint32_t bf[2][4];
            #pragma unroll
            for (int g2 = 0; g2 < 2; ++g2)
                ldsm_x4t(bf[g2], bBase + cs + ks * 4352 + g2 * 32);
            #pragma unroll
            for (int f = 0; f < 4; ++f)
                #pragma unroll
                for (int g = 0; g < 4; ++g)
                    mma_f16(d[f][g], af[f], &bf[g >> 1][(g & 1) * 2]);
        }
        cs = (cs == 2 * DN_STG) ? 0 : cs + DN_STG;
    }

    #pragma unroll
    for (int f = 0; f < 4; ++f) {
        const int r = mBase + wm * 64 + f * 16 + row4;
        #pragma unroll
        for (int g = 0; g < 4; ++g) {
            const int c = nBase + nOff + g * 8 + kq * 2;
            *(__half2*)(Out + (size_t)r * 1024 + c) =
                __floats2half2_rn(d[f][g][0], d[f][g][1]);
            *(__half2*)(Out + (size_t)(r + 8) * 1024 + c) =
                __floats2half2_rn(d[f][g][2], d[f][g][3]);
        }
    }
}

// =============================================================================
// Final combine (Y, S fp16):
// out[t] = w0*Y[inv[2t]] + w1*Y[inv[2t+1]] + sigmoid(x.gw)*S[t]
// =============================================================================
__global__ void __launch_bounds__(256) combine_kernel(
    const float* __restrict__ X, const float* __restrict__ tw,
    const float* __restrict__ gw, float* __restrict__ out)
{
    const int t = blockIdx.x;
    const int tid = threadIdx.x;
    const int lane = tid & 31, w = tid >> 5;
    __shared__ float wsum[8];

    const float4 xv = ((const float4*)(X + (size_t)t * 1024))[tid];
    const float4 gv = ((const float4*)gw)[tid];
    float acc = xv.x * gv.x + xv.y * gv.y + xv.z * gv.z + xv.w * gv.w;
    #pragma unroll
    for (int o = 16; o; o >>= 1)
        acc += __shfl_xor_sync(0xffffffffu, acc, o);
    if (lane == 0) wsum[w] = acc;
    __syncthreads();
    float tot = 0.f;
    #pragma unroll
    for (int ww = 0; ww < 8; ++ww) tot += wsum[ww];

    const float g = 1.f / (1.f + __expf(-tot));
    const int r0 = g_inv[2 * t], r1 = g_inv[2 * t + 1];
    const float w0 = tw[2 * t], w1 = tw[2 * t + 1];

    // 4 halfs (= 2 half2) per thread from each of Y0, Y1, S
    const __half2* y0 = (const __half2*)(g_Y + (size_t)r0 * 1024) + 2 * tid;
    const __half2* y1 = (const __half2*)(g_Y + (size_t)r1 * 1024) + 2 * tid;
    const __half2* sv = (const __half2*)(g_S + (size_t)t  * 1024) + 2 * tid;
    const float2 a0 = __half22float2(y0[0]), a1 = __half22float2(y0[1]);
    const float2 b0 = __half22float2(y1[0]), b1 = __half22float2(y1[1]);
    const float2 c0 = __half22float2(sv[0]), c1 = __half22float2(sv[1]);
    float4 r;
    r.x = w0 * a0.x + w1 * b0.x + g * c0.x;
    r.y = w0 * a0.y + w1 * b0.y + g * c0.y;
    r.z = w0 * a1.x + w1 * b1.x + g * c1.x;
    r.w = w0 * a1.y + w1 * b1.y + g * c1.y;
    ((float4*)(out + (size_t)t * 1024))[tid] = r;
}

// =============================================================================
extern "C" void kernel_launch(void* const* d_in, const int* in_sizes, int n_in,
                              void* d_out, int out_size) {
    (void)in_sizes; (void)n_in; (void)out_size;
    const float* X   = (const float*)d_in[0];
    const float* tw  = (const float*)d_in[1];
    const float* wg  = (const float*)d_in[2];
    const float* wu  = (const float*)d_in[3];
    const float* wd  = (const float*)d_in[4];
    const float* swg = (const float*)d_in[5];
    const float* swu = (const float*)d_in[6];
    const float* swd = (const float*)d_in[7];
    const float* gw  = (const float*)d_in[8];
    const int*   tki = (const int*)d_in[9];
    float* out = (float*)d_out;

    __half *hX, *hWg, *hWu, *hWd, *hSg, *hSu, *hSd, *H, *SH, *Y, *S;
    cudaGetSymbolAddress((void**)&hX,  g_hX);
    cudaGetSymbolAddress((void**)&hWg, g_hwg);
    cudaGetSymbolAddress((void**)&hWu, g_hwu);
    cudaGetSymbolAddress((void**)&hWd, g_hwd);
    cudaGetSymbolAddress((void**)&hSg, g_hswg);
    cudaGetSymbolAddress((void**)&hSu, g_hswu);
    cudaGetSymbolAddress((void**)&hSd, g_hswd);
    cudaGetSymbolAddress((void**)&H,   g_H);
    cudaGetSymbolAddress((void**)&SH,  g_SH);
    cudaGetSymbolAddress((void**)&Y,   g_Y);
    cudaGetSymbolAddress((void**)&S,   g_S);

    // one-time (uncaptured first call) stream/event creation — no device allocs
    static cudaStream_t s1 = nullptr;
    static cudaEvent_t evStart = nullptr, evCvt = nullptr,
                       evPerm = nullptr, evShared = nullptr;
    if (!s1) {
        cudaStreamCreateWithFlags(&s1, cudaStreamNonBlocking);
        cudaEventCreateWithFlags(&evStart,  cudaEventDisableTiming);
        cudaEventCreateWithFlags(&evCvt,    cudaEventDisableTiming);
        cudaEventCreateWithFlags(&evPerm,   cudaEventDisableTiming);
        cudaEventCreateWithFlags(&evShared, cudaEventDisableTiming);
        cudaFuncSetAttribute(gemm_gu<true >, cudaFuncAttributeMaxDynamicSharedMemorySize, GU_SMEM);
        cudaFuncSetAttribute(gemm_gu<false>, cudaFuncAttributeMaxDynamicSharedMemorySize, GU_SMEM);
        cudaFuncSetAttribute(gemm_dn,        cudaFuncAttributeMaxDynamicSharedMemorySize, DN_SMEM);
    }

    // ---- stream 0: cvt --------------------------------------------------------
    cudaEventRecord(evStart, 0);
    cvt_all<<<2368, 256>>>(X, wg, wu, wd, swg, swu, swd);
    cudaEventRecord(evCvt, 0);

    // ---- stream s1: perm (|| cvt), then shared chain ---------------------------
    cudaStreamWaitEvent(s1, evStart, 0);
    build_perm_kernel<<<NEXP, 256, 0, s1>>>(tki);
    cudaEventRecord(evPerm, s1);
    cudaStreamWaitEvent(s1, evCvt, 0);
    gemm_gu<false><<<dim3(32, 16, 1), 256, GU_SMEM, s1>>>(hX, hSg, hSu, SH);
    gemm_dn<<<dim3(32, 8, 1), 256, DN_SMEM, s1>>>(SH, hSd, S);
    cudaEventRecord(evShared, s1);

    // ---- stream 0: routed chain, then join + combine ---------------------------
    cudaStreamWaitEvent(0, evPerm, 0);
    gemm_gu<true ><<<dim3(8, 16, NEXP), 256, GU_SMEM>>>(hX, hWg, hWu, H);
    gemm_dn<<<dim3(8, 8, NEXP), 256, DN_SMEM>>>(H, hWd, Y);
    cudaStreamWaitEvent(0, evShared, 0);
    combine_kernel<<<NTOK, 256>>>(X, tw, gw, out);
}

// round 12
// speedup vs baseline: 1.0148x; 1.0070x over previous
#include <cuda_runtime.h>
#include <cuda_fp16.h>
#include <cstdint>

// =============================================================================
// MoE fused layer, plain sm_103. R12: GEMMs byte-identical to R11 (at the
// legacy-HMMA ~295 TF/s ceiling). Head/tail trims: cvt split so only
// GU-gating tensors (X, wg, wu, swg, swu) are on the critical path; wd/swd
// convert on a 3rd stream under the GU phase; shared-expert sigmoid gate
// precomputed at t=0. T=4096, D=1024, E=8, K=2, F=SF=1024.
// =============================================================================

#define NEXP   8
#define NTOK   4096
#define NROWS  8192
#define CPE    1024

// ---------------- device-global scratch --------------------------------------
__device__ __align__(16) __half g_hX  [4096u * 1024u];
__device__ __align__(16) __half g_hwg [8u * 1024u * 1024u];
__device__ __align__(16) __half g_hwu [8u * 1024u * 1024u];
__device__ __align__(16) __half g_hwd [8u * 1024u * 1024u];
__device__ __align__(16) __half g_hswg[1024u * 1024u];
__device__ __align__(16) __half g_hswu[1024u * 1024u];
__device__ __align__(16) __half g_hswd[1024u * 1024u];
__device__ __align__(16) __half g_H [8192u * 1024u];   // routed hidden
__device__ __align__(16) __half g_SH[4096u * 1024u];   // shared hidden
__device__ __align__(16) __half g_Y [8192u * 1024u];   // routed down out (fp16)
__device__ __align__(16) __half g_S [4096u * 1024u];   // shared down out (fp16)
__device__ float g_gate[4096];                          // sigmoid(X . gw)
__device__ int   g_perm[8192];
__device__ int   g_inv [8192];

// ---------------- helpers ------------------------------------------------------
__device__ __forceinline__ uint32_t smem_u32(const void* p) {
    uint32_t a;
    asm("{ .reg .u64 t; cvta.to.shared.u64 t, %1; cvt.u32.u64 %0, t; }"
        : "=r"(a) : "l"(p));
    return a;
}
__device__ __forceinline__ void cp_async16(uint32_t dst, const void* src) {
    asm volatile("cp.async.cg.shared.global [%0], [%1], 16;"
                 :: "r"(dst), "l"(src) : "memory");
}
__device__ __forceinline__ void cp_commit() {
    asm volatile("cp.async.commit_group;" ::: "memory");
}
template<int N>
__device__ __forceinline__ void cp_wait() {
    asm volatile("cp.async.wait_group %0;" :: "n"(N) : "memory");
}
__device__ __forceinline__ void ldsm_x4(uint32_t* r, uint32_t addr) {
    asm volatile("ldmatrix.sync.aligned.m8n8.x4.shared.b16 {%0,%1,%2,%3}, [%4];"
                 : "=r"(r[0]), "=r"(r[1]), "=r"(r[2]), "=r"(r[3]) : "r"(addr));
}
__device__ __forceinline__ void ldsm_x4t(uint32_t* r, uint32_t addr) {
    asm volatile("ldmatrix.sync.aligned.m8n8.x4.trans.shared.b16 {%0,%1,%2,%3}, [%4];"
                 : "=r"(r[0]), "=r"(r[1]), "=r"(r[2]), "=r"(r[3]) : "r"(addr));
}
__device__ __forceinline__ void mma_f16(float* d, const uint32_t* a,
                                        const uint32_t* b) {
    asm volatile(
        "mma.sync.aligned.m16n8k16.row.col.f32.f16.f16.f32 "
        "{%0,%1,%2,%3}, {%4,%5,%6,%7}, {%8,%9}, {%0,%1,%2,%3};"
        : "+f"(d[0]), "+f"(d[1]), "+f"(d[2]), "+f"(d[3])
        : "r"(a[0]), "r"(a[1]), "r"(a[2]), "r"(a[3]), "r"(b[0]), "r"(b[1]));
}
__device__ __forceinline__ float silu(float x) {
    return x / (1.f + __expf(-x));
}

// =============================================================================
// cvtA: GU-gating tensors. X(1048576) wg(2097152) wu(2097152) swg(262144)
// swu(262144) = 5767168 float4 units.
// =============================================================================
__global__ void __launch_bounds__(256) cvt_A(
    const float* __restrict__ x,
    const float* __restrict__ wg,  const float* __restrict__ wu,
    const float* __restrict__ swg, const float* __restrict__ swu)
{
    const size_t total = 5767168u;
    for (size_t i = (size_t)blockIdx.x * blockDim.x + threadIdx.x;
         i < total; i += (size_t)gridDim.x * blockDim.x) {
        const float4* s; __half2* d; size_t j;
        if      (i < 1048576u) { s = (const float4*)x;   d = (__half2*)g_hX;   j = i; }
        else if (i < 3145728u) { s = (const float4*)wg;  d = (__half2*)g_hwg;  j = i - 1048576u; }
        else if (i < 5242880u) { s = (const float4*)wu;  d = (__half2*)g_hwu;  j = i - 3145728u; }
        else if (i < 5505024u) { s = (const float4*)swg; d = (__half2*)g_hswg; j = i - 5242880u; }
        else                   { s = (const float4*)swu; d = (__half2*)g_hswu; j = i - 5505024u; }
        const float4 v = s[j];
        d[2 * j]     = __floats2half2_rn(v.x, v.y);
        d[2 * j + 1] = __floats2half2_rn(v.z, v.w);
    }
}

// cvtB: down-projection weights. wd(2097152) swd(262144) = 2359296 f4.
// Runs on a side stream under the GU phase; modest grid to limit displacement.
__global__ void __launch_bounds__(256) cvt_B(
    const float* __restrict__ wd, const float* __restrict__ swd)
{
    const size_t total = 2359296u;
    for (size_t i = (size_t)blockIdx.x * blockDim.x + threadIdx.x;
         i < total; i += (size_t)gridDim.x * blockDim.x) {
        const float4* s; __half2* d; size_t j;
        if (i < 2097152u) { s = (const float4*)wd;  d = (__half2*)g_hwd;  j = i; }
        else              { s = (const float4*)swd; d = (__half2*)g_hswd; j = i - 2097152u; }
        const float4 v = s[j];
        d[2 * j]     = __floats2half2_rn(v.x, v.y);
        d[2 * j + 1] = __floats2half2_rn(v.z, v.w);
    }
}

// =============================================================================
// Shared-expert sigmoid gate: g_gate[t] = sigmoid(X[t] . gw). Warp per token.
// =============================================================================
__global__ void __launch_bounds__(256) gate_kernel(
    const float* __restrict__ X, const float* __restrict__ gw)
{
    const int w    = threadIdx.x >> 5;
    const int lane = threadIdx.x & 31;
    const int t    = blockIdx.x * 8 + w;
    const float4* xr = (const float4*)(X + (size_t)t * 1024);
    const float4* gr = (const float4*)gw;
    float acc = 0.f;
    #pragma unroll
    for (int i = 0; i < 8; ++i) {
        const float4 a = xr[lane + i * 32];
        const float4 b = gr[lane + i * 32];
        acc += a.x * b.x + a.y * b.y + a.z * b.z + a.w * b.w;
    }
    #pragma unroll
    for (int o = 16; o; o >>= 1)
        acc += __shfl_xor_sync(0xffffffffu, acc, o);
    if (lane == 0)
        g_gate[t] = 1.f / (1.f + __expf(-acc));
}

// =============================================================================
// Stable counting-sort permutation via warp ballots.
// =============================================================================
__global__ void build_perm_kernel(const int* __restrict__ tki) {
    const int e    = blockIdx.x;
    const int tid  = threadIdx.x;
    const int lane = tid & 31;
    const int w    = tid >> 5;
    __shared__ int wcnt[8];
    __shared__ int basev;
    if (tid == 0) basev = 0;
    __syncthreads();
    for (int start = 0; start < NROWS; start += 256) {
        const int i = start + tid;
        const bool m = (tki[i] == e);
        const uint32_t mask = __ballot_sync(0xffffffffu, m);
        if (lane == 0) wcnt[w] = __popc(mask);
        __syncthreads();
        int wpre = 0, tot = 0;
        #pragma unroll
        for (int ww = 0; ww < 8; ++ww) {
            const int c = wcnt[ww];
            wpre += (ww < w) ? c : 0;
            tot  += c;
        }
        if (m) {
            const int rank = __popc(mask & ((1u << lane) - 1u));
            const int dest = e * CPE + basev + wpre + rank;
            g_perm[dest] = i;
            g_inv[i] = dest;
        }
        __syncthreads();
        if (tid == 0) basev += tot;
        __syncthreads();
    }
}

// =============================================================================
// Fused gate+up GEMM (R8 verbatim — ceiling-bound, do not touch).
// =============================================================================
#define GU_STG   36864
#define GU_SMEM  (3 * GU_STG + 512)

template<bool GATHER>
__global__ void __launch_bounds__(256, 2) gemm_gu(
    const __half* __restrict__ A,
    const __half* __restrict__ B0g,
    const __half* __restrict__ B1g,
    __half* __restrict__ Out)
{
    extern __shared__ char sm[];
    const uint32_t smem = smem_u32(sm);
    int* srcRow = (int*)(sm + 3 * GU_STG);

    const int tid  = threadIdx.x;
    const int wid  = tid >> 5;
    const int lane = tid & 31;
    const int row4 = lane >> 2;
    const int kq   = lane & 3;
    const int rl   = lane & 7;
    const int sel  = lane >> 3;
    const int mat  = wid >> 2;
    const int wm   = (wid >> 1) & 1;
    const int wn2  = wid & 1;

    const int mBase = (blockIdx.z * gridDim.x + blockIdx.x) * 128;
    const int nBase = blockIdx.y * 64;

    if (tid < 128)
        srcRow[tid] = GATHER ? (g_perm[mBase + tid] >> 1) : (mBase + tid);
    __syncthreads();

    const __half* B0 = B0g + (size_t)blockIdx.z * 1048576u;
    const __half* B1 = B1g + (size_t)blockIdx.z * 1048576u;

    const __half* aSrc[4]; uint32_t aDst[4];
    const __half* bSrc[4]; uint32_t bDst[4];
    #pragma unroll
    for (int it = 0; it < 4; ++it) {
        const int ia = tid + it * 256;
        const int r = ia >> 3, q = ia & 7;
        aSrc[it] = A + (size_t)srcRow[r] * 1024 + q * 8;
        aDst[it] = smem + r * 144 + q * 16;
        const int mm = ia >> 9, kr = (ia >> 3) & 63, qb = ia & 7;
        bSrc[it] = (mm ? B1 : B0) + (size_t)kr * 1024 + nBase + qb * 8;
        bDst[it] = smem + 18432 + mm * 9216 + kr * 144 + qb * 16;
    }

    const uint32_t aBase = smem + (wm * 64 + (sel & 1) * 8 + rl) * 144
                         + (sel >> 1) * 16;
    const uint32_t bBase = smem + 18432 + mat * 9216
                         + ((sel & 1) * 8 + rl) * 144
                         + (wn2 * 32 + (sel >> 1) * 8) * 2;

    float d[4][4][4];
    #pragma unroll
    for (int f = 0; f < 4; ++f)
        #pragma unroll
        for (int g = 0; g < 4; ++g)
            #pragma unroll
            for (int j = 0; j < 4; ++j) d[f][g][j] = 0.f;

    auto issue = [&](int ch, uint32_t soff) {
        const int k0 = ch * 64;
        #pragma unroll
        for (int it = 0; it < 4; ++it)
            cp_async16(aDst[it] + soff, aSrc[it] + k0);
        #pragma unroll
        for (int it = 0; it < 4; ++it)
            cp_async16(bDst[it] + soff, bSrc[it] + (size_t)k0 * 1024);
        cp_commit();
    };

    issue(0, 0);
    issue(1, GU_STG);

    uint32_t cs = 0, ns = 2 * GU_STG;
    for (int ch = 0; ch < 16; ++ch) {
        if (ch < 15) cp_wait<1>(); else cp_wait<0>();
        __syncthreads();
        if (ch < 14) {
            issue(ch + 2, ns);
            ns = (ns == 2 * GU_STG) ? 0 : ns + GU_STG;
        }
        #pragma unroll
        for (int ks = 0; ks < 4; ++ks) {
            uint32_t af[4][4];
            #pragma unroll
            for (int f = 0; f < 4; ++f)
                ldsm_x4(af[f], aBase + cs + f * 2304 + ks * 32);
            uint32_t bf[2][4];
            #pragma unroll
            for (int g2 = 0; g2 < 2; ++g2)
                ldsm_x4t(bf[g2], bBase + cs + ks * 2304 + g2 * 32);
            #pragma unroll
            for (int f = 0; f < 4; ++f)
                #pragma unroll
                for (int g = 0; g < 4; ++g)
                    mma_f16(d[f][g], af[f], &bf[g >> 1][(g & 1) * 2]);
        }
        cs = (cs == 2 * GU_STG) ? 0 : cs + GU_STG;
    }

    __syncthreads();
    float* Us = (float*)sm;             // [128][66]
    if (mat == 1) {
        #pragma unroll
        for (int f = 0; f < 4; ++f) {
            const int r = wm * 64 + f * 16 + row4;
            #pragma unroll
            for (int g = 0; g < 4; ++g) {
                const int c = wn2 * 32 + g * 8 + kq * 2;
                *(float2*)(Us + r * 66 + c)       = make_float2(d[f][g][0], d[f][g][1]);
                *(float2*)(Us + (r + 8) * 66 + c) = make_float2(d[f][g][2], d[f][g][3]);
            }
        }
    }
    __syncthreads();
    if (mat == 0) {
        #pragma unroll
        for (int f = 0; f < 4; ++f) {
            const int r = wm * 64 + f * 16 + row4;
            #pragma unroll
            for (int g = 0; g < 4; ++g) {
                const int c = wn2 * 32 + g * 8 + kq * 2;
                const float2 u0 = *(const float2*)(Us + r * 66 + c);
                const float2 u1 = *(const float2*)(Us + (r + 8) * 66 + c);
                *(__half2*)(Out + (size_t)(mBase + r) * 1024 + nBase + c) =
                    __floats2half2_rn(silu(d[f][g][0]) * u0.x,
                                      silu(d[f][g][1]) * u0.y);
                *(__half2*)(Out + (size_t)(mBase + r + 8) * 1024 + nBase + c) =
                    __floats2half2_rn(silu(d[f][g][2]) * u1.x,
                                      silu(d[f][g][3]) * u1.y);
            }
        }
    }
}

// =============================================================================
// Down GEMM (R11 verbatim — fp16 out).
// =============================================================================
#define DN_STG   35840
#define DN_SMEM  (3 * DN_STG + 256)

__global__ void __launch_bounds__(256, 2) gemm_dn(
    const __half* __restrict__ A,
    const __half* __restrict__ Bg,
    __half* __restrict__ Out)
{
    extern __shared__ char sm[];
    const uint32_t smem = smem_u32(sm);

    const int tid  = threadIdx.x;
    const int wid  = tid >> 5;
    const int lane = tid & 31;
    const int row4 = lane >> 2;
    const int kq   = lane & 3;
    const int rl   = lane & 7;
    const int sel  = lane >> 3;
    const int wm   = wid & 1;
    const int nOff = (wid >> 1) * 32;

    const int mBase = (blockIdx.z * gridDim.x + blockIdx.x) * 128;
    const int nBase = blockIdx.y * 128;

    const __half* B = Bg + (size_t)blockIdx.z * (1024u * 1024u);

    const __half* aSrc[4]; uint32_t aDst[4];
    const __half* bSrc[4]; uint32_t bDst[4];
    #pragma unroll
    for (int it = 0; it < 4; ++it) {
        const int ia = tid + it * 256;
        const int r = ia >> 3, q = ia & 7;
        aSrc[it] = A + (size_t)(mBase + r) * 1024 + q * 8;
        aDst[it] = smem + r * 144 + q * 16;
        const int kr = ia >> 4, qb = ia & 15;
        bSrc[it] = B + (size_t)kr * 1024 + nBase + qb * 8;
        bDst[it] = smem + 18432 + kr * 272 + qb * 16;
    }

    const uint32_t aBase = smem + (wm * 64 + (sel & 1) * 8 + rl) * 144
                         + (sel >> 1) * 16;
    const uint32_t bBase = smem + 18432 + ((sel & 1) * 8 + rl) * 272
                         + (nOff + (sel >> 1) * 8) * 2;

    float d[4][4][4];
    #pragma unroll
    for (int f = 0; f < 4; ++f)
        #pragma unroll
        for (int g = 0; g < 4; ++g)
            #pragma unroll
            for (int j = 0; j < 4; ++j) d[f][g][j] = 0.f;

    auto issue = [&](int ch, uint32_t soff) {
        const int k0 = ch * 64;
        #pragma unroll
        for (int it = 0; it < 4; ++it)
            cp_async16(aDst[it] + soff, aSrc[it] + k0);
        #pragma unroll
        for (int it = 0; it < 4; ++it)
            cp_async16(bDst[it] + soff, bSrc[it] + (size_t)k0 * 1024);
        cp_commit();
    };

    issue(0, 0);
    issue(1, DN_STG);

    uint32_t cs = 0, ns = 2 * DN_STG;
    for (int ch = 0; ch < 16; ++ch) {
        if (ch < 15) cp_wait<1>(); else cp_wait<0>();
        __syncthreads();
        if (ch < 14) {
            issue(ch + 2, ns);
            ns = (ns == 2 * DN_STG) ? 0 : ns + DN_STG;
        }
        #pragma unroll
        for (int ks = 0; ks < 4; ++ks) {
            uint32_t af[4][4];
            #pragma unroll
            for (int f = 0; f < 4; ++f)
                ldsm_x4(af[f], aBase + cs + f * 2304 + ks * 32);
            uint32_t bf[2][4];
            #pragma unroll
            for (int g2 = 0; g2 < 2; ++g2)
                ldsm_x4t(bf[g2], bBase + cs + ks * 4352 + g2 * 32);
            #pragma unroll
            for (int f = 0; f < 4; ++f)
                #pragma unroll
                for (int g = 0; g < 4; ++g)
                    mma_f16(d[f][g], af[f], &bf[g >> 1][(g & 1) * 2]);
        }
        cs = (cs == 2 * DN_STG) ? 0 : cs + DN_STG;
    }

    #pragma unroll
    for (int f = 0; f < 4; ++f) {
        const int r = mBase + wm * 64 + f * 16 + row4;
        #pragma unroll
        for (int g = 0; g < 4; ++g) {
            const int c = nBase + nOff + g * 8 + kq * 2;
            *(__half2*)(Out + (size_t)r * 1024 + c) =
                __floats2half2_rn(d[f][g][0], d[f][g][1]);
            *(__half2*)(Out + (size_t)(r + 8) * 1024 + c) =
                __floats2half2_rn(d[f][g][2], d[f][g][3]);
        }
    }
}

// =============================================================================
// Final combine: out[t] = w0*Y[inv[2t]] + w1*Y[inv[2t+1]] + g_gate[t]*S[t]
// =============================================================================
__global__ void __launch_bounds__(256) combine_kernel(
    const float* __restrict__ tw, float* __restrict__ out)
{
    const int t = blockIdx.x;
    const int tid = threadIdx.x;

    const float g = g_gate[t];
    const int r0 = g_inv[2 * t], r1 = g_inv[2 * t + 1];
    const float w0 = tw[2 * t], w1 = tw[2 * t + 1];

    const __half2* y0 = (const __half2*)(g_Y + (size_t)r0 * 1024) + 2 * tid;
    const __half2* y1 = (const __half2*)(g_Y + (size_t)r1 * 1024) + 2 * tid;
    const __half2* sv = (const __half2*)(g_S + (size_t)t  * 1024) + 2 * tid;
    const float2 a0 = __half22float2(y0[0]), a1 = __half22float2(y0[1]);
    const float2 b0 = __half22float2(y1[0]), b1 = __half22float2(y1[1]);
    const float2 c0 = __half22float2(sv[0]), c1 = __half22float2(sv[1]);
    float4 r;
    r.x = w0 * a0.x + w1 * b0.x + g * c0.x;
    r.y = w0 * a0.y + w1 * b0.y + g * c0.y;
    r.z = w0 * a1.x + w1 * b1.x + g * c1.x;
    r.w = w0 * a1.y + w1 * b1.y + g * c1.y;
    ((float4*)(out + (size_t)t * 1024))[tid] = r;
}

// =============================================================================
extern "C" void kernel_launch(void* const* d_in, const int* in_sizes, int n_in,
                              void* d_out, int out_size) {
    (void)in_sizes; (void)n_in; (void)out_size;
    const float* X   = (const float*)d_in[0];
    const float* tw  = (const float*)d_in[1];
    const float* wg  = (const float*)d_in[2];
    const float* wu  = (const float*)d_in[3];
    const float* wd  = (const float*)d_in[4];
    const float* swg = (const float*)d_in[5];
    const float* swu = (const float*)d_in[6];
    const float* swd = (const float*)d_in[7];
    const float* gw  = (const float*)d_in[8];
    const int*   tki = (const int*)d_in[9];
    float* out = (float*)d_out;

    __half *hX, *hWg, *hWu, *hWd, *hSg, *hSu, *hSd, *H, *SH, *Y, *S;
    cudaGetSymbolAddress((void**)&hX,  g_hX);
    cudaGetSymbolAddress((void**)&hWg, g_hwg);
    cudaGetSymbolAddress((void**)&hWu, g_hwu);
    cudaGetSymbolAddress((void**)&hWd, g_hwd);
    cudaGetSymbolAddress((void**)&hSg, g_hswg);
    cudaGetSymbolAddress((void**)&hSu, g_hswu);
    cudaGetSymbolAddress((void**)&hSd, g_hswd);
    cudaGetSymbolAddress((void**)&H,   g_H);
    cudaGetSymbolAddress((void**)&SH,  g_SH);
    cudaGetSymbolAddress((void**)&Y,   g_Y);
    cudaGetSymbolAddress((void**)&S,   g_S);

    // one-time (uncaptured first call) stream/event creation — no device allocs
    static cudaStream_t s1 = nullptr, s2 = nullptr;
    static cudaEvent_t evStart = nullptr, evCvtA = nullptr, evCvtB = nullptr,
                       evPerm = nullptr, evShared = nullptr, evGate = nullptr;
    if (!s1) {
        cudaStreamCreateWithFlags(&s1, cudaStreamNonBlocking);
        cudaStreamCreateWithFlags(&s2, cudaStreamNonBlocking);
        cudaEventCreateWithFlags(&evStart,  cudaEventDisableTiming);
        cudaEventCreateWithFlags(&evCvtA,   cudaEventDisableTiming);
        cudaEventCreateWithFlags(&evCvtB,   cudaEventDisableTiming);
        cudaEventCreateWithFlags(&evPerm,   cudaEventDisableTiming);
        cudaEventCreateWithFlags(&evShared, cudaEventDisableTiming);
        cudaEventCreateWithFlags(&evGate,   cudaEventDisableTiming);
        cudaFuncSetAttribute(gemm_gu<true >, cudaFuncAttributeMaxDynamicSharedMemorySize, GU_SMEM);
        cudaFuncSetAttribute(gemm_gu<false>, cudaFuncAttributeMaxDynamicSharedMemorySize, GU_SMEM);
        cudaFuncSetAttribute(gemm_dn,        cudaFuncAttributeMaxDynamicSharedMemorySize, DN_SMEM);
    }

    // ---- stream 0: cvtA (GU-gating tensors) -----------------------------------
    cudaEventRecord(evStart, 0);
    cvt_A<<<2368, 256>>>(X, wg, wu, swg, swu);
    cudaEventRecord(evCvtA, 0);

    // ---- stream s2: gate(X) at t=0, then cvtB under the GU phase ---------------
    cudaStreamWaitEvent(s2, evStart, 0);
    gate_kernel<<<512, 256, 0, s2>>>(X, gw);
    cudaEventRecord(evGate, s2);
    cudaStreamWaitEvent(s2, evCvtA, 0);
    cvt_B<<<592, 256, 0, s2>>>(wd, swd);
    cudaEventRecord(evCvtB, s2);

    // ---- stream s1: perm (|| cvtA), then shared chain ---------------------------
    cudaStreamWaitEvent(s1, evStart, 0);
    build_perm_kernel<<<NEXP, 256, 0, s1>>>(tki);
    cudaEventRecord(evPerm, s1);
    cudaStreamWaitEvent(s1, evCvtA, 0);
    gemm_gu<false><<<dim3(32, 16, 1), 256, GU_SMEM, s1>>>(hX, hSg, hSu, SH);
    cudaStreamWaitEvent(s1, evCvtB, 0);
    gemm_dn<<<dim3(32, 8, 1), 256, DN_SMEM, s1>>>(SH, hSd, S);
    cudaEventRecord(evShared, s1);

    // ---- stream 0: routed chain, then join + combine ---------------------------
    cudaStreamWaitEvent(0, evPerm, 0);
    gemm_gu<true ><<<dim3(8, 16, NEXP), 256, GU_SMEM>>>(hX, hWg, hWu, H);
    cudaStreamWaitEvent(0, evCvtB, 0);
    gemm_dn<<<dim3(8, 8, NEXP), 256, DN_SMEM>>>(H, hWd, Y);
    cudaStreamWaitEvent(0, evShared, 0);
    cudaStreamWaitEvent(0, evGate, 0);
    combine_kernel<<<NTOK, 256>>>(tw, out);
}

// round 13
// speedup vs baseline: 1.0224x; 1.0075x over previous
#include <cuda_runtime.h>
#include <cuda_fp16.h>
#include <cstdint>

// =============================================================================
// MoE fused layer, plain sm_103. R13: GEMMs byte-identical to R11/R12.
// Conversion re-cut by consumer: cvtS (X,swg,swu) releases the shared GU
// ~18 us earlier; cvtR (wg,wu) gates the routed GU; perm moved off the
// shared-chain stream. T=4096, D=1024, E=8, K=2, F=SF=1024.
// =============================================================================

#define NEXP   8
#define NTOK   4096
#define NROWS  8192
#define CPE    1024

// ---------------- device-global scratch --------------------------------------
__device__ __align__(16) __half g_hX  [4096u * 1024u];
__device__ __align__(16) __half g_hwg [8u * 1024u * 1024u];
__device__ __align__(16) __half g_hwu [8u * 1024u * 1024u];
__device__ __align__(16) __half g_hwd [8u * 1024u * 1024u];
__device__ __align__(16) __half g_hswg[1024u * 1024u];
__device__ __align__(16) __half g_hswu[1024u * 1024u];
__device__ __align__(16) __half g_hswd[1024u * 1024u];
__device__ __align__(16) __half g_H [8192u * 1024u];   // routed hidden
__device__ __align__(16) __half g_SH[4096u * 1024u];   // shared hidden
__device__ __align__(16) __half g_Y [8192u * 1024u];   // routed down out (fp16)
__device__ __align__(16) __half g_S [4096u * 1024u];   // shared down out (fp16)
__device__ float g_gate[4096];                          // sigmoid(X . gw)
__device__ int   g_perm[8192];
__device__ int   g_inv [8192];

// ---------------- helpers ------------------------------------------------------
__device__ __forceinline__ uint32_t smem_u32(const void* p) {
    uint32_t a;
    asm("{ .reg .u64 t; cvta.to.shared.u64 t, %1; cvt.u32.u64 %0, t; }"
        : "=r"(a) : "l"(p));
    return a;
}
__device__ __forceinline__ void cp_async16(uint32_t dst, const void* src) {
    asm volatile("cp.async.cg.shared.global [%0], [%1], 16;"
                 :: "r"(dst), "l"(src) : "memory");
}
__device__ __forceinline__ void cp_commit() {
    asm volatile("cp.async.commit_group;" ::: "memory");
}
template<int N>
__device__ __forceinline__ void cp_wait() {
    asm volatile("cp.async.wait_group %0;" :: "n"(N) : "memory");
}
__device__ __forceinline__ void ldsm_x4(uint32_t* r, uint32_t addr) {
    asm volatile("ldmatrix.sync.aligned.m8n8.x4.shared.b16 {%0,%1,%2,%3}, [%4];"
                 : "=r"(r[0]), "=r"(r[1]), "=r"(r[2]), "=r"(r[3]) : "r"(addr));
}
__device__ __forceinline__ void ldsm_x4t(uint32_t* r, uint32_t addr) {
    asm volatile("ldmatrix.sync.aligned.m8n8.x4.trans.shared.b16 {%0,%1,%2,%3}, [%4];"
                 : "=r"(r[0]), "=r"(r[1]), "=r"(r[2]), "=r"(r[3]) : "r"(addr));
}
__device__ __forceinline__ void mma_f16(float* d, const uint32_t* a,
                                        const uint32_t* b) {
    asm volatile(
        "mma.sync.aligned.m16n8k16.row.col.f32.f16.f16.f32 "
        "{%0,%1,%2,%3}, {%4,%5,%6,%7}, {%8,%9}, {%0,%1,%2,%3};"
        : "+f"(d[0]), "+f"(d[1]), "+f"(d[2]), "+f"(d[3])
        : "r"(a[0]), "r"(a[1]), "r"(a[2]), "r"(a[3]), "r"(b[0]), "r"(b[1]));
}
__device__ __forceinline__ float silu(float x) {
    return x / (1.f + __expf(-x));
}

// =============================================================================
// cvtS: shared-GU-gating tensors. X(1048576) swg(262144) swu(262144)
//       = 1572864 float4 units.
// cvtR: routed-GU weights. wg(2097152) wu(2097152) = 4194304 f4.
// cvtB: down weights. wd(2097152) swd(262144) = 2359296 f4.
// =============================================================================
__global__ void __launch_bounds__(256) cvt_S(
    const float* __restrict__ x,
    const float* __restrict__ swg, const float* __restrict__ swu)
{
    const size_t total = 1572864u;
    for (size_t i = (size_t)blockIdx.x * blockDim.x + threadIdx.x;
         i < total; i += (size_t)gridDim.x * blockDim.x) {
        const float4* s; __half2* d; size_t j;
        if      (i < 1048576u) { s = (const float4*)x;   d = (__half2*)g_hX;   j = i; }
        else if (i < 1310720u) { s = (const float4*)swg; d = (__half2*)g_hswg; j = i - 1048576u; }
        else                   { s = (const float4*)swu; d = (__half2*)g_hswu; j = i - 1310720u; }
        const float4 v = s[j];
        d[2 * j]     = __floats2half2_rn(v.x, v.y);
        d[2 * j + 1] = __floats2half2_rn(v.z, v.w);
    }
}

__global__ void __launch_bounds__(256) cvt_R(
    const float* __restrict__ wg, const float* __restrict__ wu)
{
    const size_t total = 4194304u;
    for (size_t i = (size_t)blockIdx.x * blockDim.x + threadIdx.x;
         i < total; i += (size_t)gridDim.x * blockDim.x) {
        const float4* s; __half2* d; size_t j;
        if (i < 2097152u) { s = (const float4*)wg; d = (__half2*)g_hwg; j = i; }
        else              { s = (const float4*)wu; d = (__half2*)g_hwu; j = i - 2097152u; }
        const float4 v = s[j];
        d[2 * j]     = __floats2half2_rn(v.x, v.y);
        d[2 * j + 1] = __floats2half2_rn(v.z, v.w);
    }
}

__global__ void __launch_bounds__(256) cvt_B(
    const float* __restrict__ wd, const float* __restrict__ swd)
{
    const size_t total = 2359296u;
    for (size_t i = (size_t)blockIdx.x * blockDim.x + threadIdx.x;
         i < total; i += (size_t)gridDim.x * blockDim.x) {
        const float4* s; __half2* d; size_t j;
        if (i < 2097152u) { s = (const float4*)wd;  d = (__half2*)g_hwd;  j = i; }
        else              { s = (const float4*)swd; d = (__half2*)g_hswd; j = i - 2097152u; }
        const float4 v = s[j];
        d[2 * j]     = __floats2half2_rn(v.x, v.y);
        d[2 * j + 1] = __floats2half2_rn(v.z, v.w);
    }
}

// =============================================================================
// Shared-expert sigmoid gate: g_gate[t] = sigmoid(X[t] . gw). Warp per token.
// =============================================================================
__global__ void __launch_bounds__(256) gate_kernel(
    const float* __restrict__ X, const float* __restrict__ gw)
{
    const int w    = threadIdx.x >> 5;
    const int lane = threadIdx.x & 31;
    const int t    = blockIdx.x * 8 + w;
    const float4* xr = (const float4*)(X + (size_t)t * 1024);
    const float4* gr = (const float4*)gw;
    float acc = 0.f;
    #pragma unroll
    for (int i = 0; i < 8; ++i) {
        const float4 a = xr[lane + i * 32];
        const float4 b = gr[lane + i * 32];
        acc += a.x * b.x + a.y * b.y + a.z * b.z + a.w * b.w;
    }
    #pragma unroll
    for (int o = 16; o; o >>= 1)
        acc += __shfl_xor_sync(0xffffffffu, acc, o);
    if (lane == 0)
        g_gate[t] = 1.f / (1.f + __expf(-acc));
}

// =============================================================================
// Stable counting-sort permutation via warp ballots.
// =============================================================================
__global__ void build_perm_kernel(const int* __restrict__ tki) {
    const int e    = blockIdx.x;
    const int tid  = threadIdx.x;
    const int lane = tid & 31;
    const int w    = tid >> 5;
    __shared__ int wcnt[8];
    __shared__ int basev;
    if (tid == 0) basev = 0;
    __syncthreads();
    for (int start = 0; start < NROWS; start += 256) {
        const int i = start + tid;
        const bool m = (tki[i] == e);
        const uint32_t mask = __ballot_sync(0xffffffffu, m);
        if (lane == 0) wcnt[w] = __popc(mask);
        __syncthreads();
        int wpre = 0, tot = 0;
        #pragma unroll
        for (int ww = 0; ww < 8; ++ww) {
            const int c = wcnt[ww];
            wpre += (ww < w) ? c : 0;
            tot  += c;
        }
        if (m) {
            const int rank = __popc(mask & ((1u << lane) - 1u));
            const int dest = e * CPE + basev + wpre + rank;
            g_perm[dest] = i;
            g_inv[i] = dest;
        }
        __syncthreads();
        if (tid == 0) basev += tot;
        __syncthreads();
    }
}

// =============================================================================
// Fused gate+up GEMM (R8 verbatim — ceiling-bound, do not touch).
// =============================================================================
#define GU_STG   36864
#define GU_SMEM  (3 * GU_STG + 512)

template<bool GATHER>
__global__ void __launch_bounds__(256, 2) gemm_gu(
    const __half* __restrict__ A,
    const __half* __restrict__ B0g,
    const __half* __restrict__ B1g,
    __half* __restrict__ Out)
{
    extern __shared__ char sm[];
    const uint32_t smem = smem_u32(sm);
    int* srcRow = (int*)(sm + 3 * GU_STG);

    const int tid  = threadIdx.x;
    const int wid  = tid >> 5;
    const int lane = tid & 31;
    const int row4 = lane >> 2;
    const int kq   = lane & 3;
    const int rl   = lane & 7;
    const int sel  = lane >> 3;
    const int mat  = wid >> 2;
    const int wm   = (wid >> 1) & 1;
    const int wn2  = wid & 1;

    const int mBase = (blockIdx.z * gridDim.x + blockIdx.x) * 128;
    const int nBase = blockIdx.y * 64;

    if (tid < 128)
        srcRow[tid] = GATHER ? (g_perm[mBase + tid] >> 1) : (mBase + tid);
    __syncthreads();

    const __half* B0 = B0g + (size_t)blockIdx.z * 1048576u;
    const __half* B1 = B1g + (size_t)blockIdx.z * 1048576u;

    const __half* aSrc[4]; uint32_t aDst[4];
    const __half* bSrc[4]; uint32_t bDst[4];
    #pragma unroll
    for (int it = 0; it < 4; ++it) {
        const int ia = tid + it * 256;
        const int r = ia >> 3, q = ia & 7;
        aSrc[it] = A + (size_t)srcRow[r] * 1024 + q * 8;
        aDst[it] = smem + r * 144 + q * 16;
        const int mm = ia >> 9, kr = (ia >> 3) & 63, qb = ia & 7;
        bSrc[it] = (mm ? B1 : B0) + (size_t)kr * 1024 + nBase + qb * 8;
        bDst[it] = smem + 18432 + mm * 9216 + kr * 144 + qb * 16;
    }

    const uint32_t aBase = smem + (wm * 64 + (sel & 1) * 8 + rl) * 144
                         + (sel >> 1) * 16;
    const uint32_t bBase = smem + 18432 + mat * 9216
                         + ((sel & 1) * 8 + rl) * 144
                         + (wn2 * 32 + (sel >> 1) * 8) * 2;

    float d[4][4][4];
    #pragma unroll
    for (int f = 0; f < 4; ++f)
        #pragma unroll
        for (int g = 0; g < 4; ++g)
            #pragma unroll
            for (int j = 0; j < 4; ++j) d[f][g][j] = 0.f;

    auto issue = [&](int ch, uint32_t soff) {
        const int k0 = ch * 64;
        #pragma unroll
        for (int it = 0; it < 4; ++it)
            cp_async16(aDst[it] + soff, aSrc[it] + k0);
        #pragma unroll
        for (int it = 0; it < 4; ++it)
            cp_async16(bDst[it] + soff, bSrc[it] + (size_t)k0 * 1024);
        cp_commit();
    };

    issue(0, 0);
    issue(1, GU_STG);

    uint32_t cs = 0, ns = 2 * GU_STG;
    for (int ch = 0; ch < 16; ++ch) {
        if (ch < 15) cp_wait<1>(); else cp_wait<0>();
        __syncthreads();
        if (ch < 14) {
            issue(ch + 2, ns);
            ns = (ns == 2 * GU_STG) ? 0 : ns + GU_STG;
        }
        #pragma unroll
        for (int ks = 0; ks < 4; ++ks) {
            uint32_t af[4][4];
            #pragma unroll
            for (int f = 0; f < 4; ++f)
                ldsm_x4(af[f], aBase + cs + f * 2304 + ks * 32);
            uint32_t bf[2][4];
            #pragma unroll
            for (int g2 = 0; g2 < 2; ++g2)
                ldsm_x4t(bf[g2], bBase + cs + ks * 2304 + g2 * 32);
            #pragma unroll
            for (int f = 0; f < 4; ++f)
                #pragma unroll
                for (int g = 0; g < 4; ++g)
                    mma_f16(d[f][g], af[f], &bf[g >> 1][(g & 1) * 2]);
        }
        cs = (cs == 2 * GU_STG) ? 0 : cs + GU_STG;
    }

    __syncthreads();
    float* Us = (float*)sm;             // [128][66]
    if (mat == 1) {
        #pragma unroll
        for (int f = 0; f < 4; ++f) {
            const int r = wm * 64 + f * 16 + row4;
            #pragma unroll
            for (int g = 0; g < 4; ++g) {
                const int c = wn2 * 32 + g * 8 + kq * 2;
                *(float2*)(Us + r * 66 + c)       = make_float2(d[f][g][0], d[f][g][1]);
                *(float2*)(Us + (r + 8) * 66 + c) = make_float2(d[f][g][2], d[f][g][3]);
            }
        }
    }
    __syncthreads();
    if (mat == 0) {
        #pragma unroll
        for (int f = 0; f < 4; ++f) {
            const int r = wm * 64 + f * 16 + row4;
            #pragma unroll
            for (int g = 0; g < 4; ++g) {
                const int c = wn2 * 32 + g * 8 + kq * 2;
                const float2 u0 = *(const float2*)(Us + r * 66 + c);
                const float2 u1 = *(const float2*)(Us + (r + 8) * 66 + c);
                *(__half2*)(Out + (size_t)(mBase + r) * 1024 + nBase + c) =
                    __floats2half2_rn(silu(d[f][g][0]) * u0.x,
                                      silu(d[f][g][1]) * u0.y);
                *(__half2*)(Out + (size_t)(mBase + r + 8) * 1024 + nBase + c) =
                    __floats2half2_rn(silu(d[f][g][2]) * u1.x,
                                      silu(d[f][g][3]) * u1.y);
            }
        }
    }
}

// =============================================================================
// Down GEMM (R11 verbatim — fp16 out).
// =============================================================================
#define DN_STG   35840
#define DN_SMEM  (3 * DN_STG + 256)

__global__ void __launch_bounds__(256, 2) gemm_dn(
    const __half* __restrict__ A,
    const __half* __restrict__ Bg,
    __half* __restrict__ Out)
{
    extern __shared__ char sm[];
    const uint32_t smem = smem_u32(sm);

    const int tid  = threadIdx.x;
    const int wid  = tid >> 5;
    const int lane = tid & 31;
    const int row4 = lane >> 2;
    const int kq   = lane & 3;
    const int rl   = lane & 7;
    const int sel  = lane >> 3;
    const int wm   = wid & 1;
    const int nOff = (wid >> 1) * 32;

    const int mBase = (blockIdx.z * gridDim.x + blockIdx.x) * 128;
    const int nBase = blockIdx.y * 128;

    const __half* B = Bg + (size_t)blockIdx.z * (1024u * 1024u);

    const __half* aSrc[4]; uint32_t aDst[4];
    const __half* bSrc[4]; uint32_t bDst[4];
    #pragma unroll
    for (int it = 0; it < 4; ++it) {
        const int ia = tid + it * 256;
        const int r = ia >> 3, q = ia & 7;
        aSrc[it] = A + (size_t)(mBase + r) * 1024 + q * 8;
        aDst[it] = smem + r * 144 + q * 16;
        const int kr = ia >> 4, qb = ia & 15;
        bSrc[it] = B + (size_t)kr * 1024 + nBase + qb * 8;
        bDst[it] = smem + 18432 + kr * 272 + qb * 16;
    }

    const uint32_t aBase = smem + (wm * 64 + (sel & 1) * 8 + rl) * 144
                         + (sel >> 1) * 16;
    const uint32_t bBase = smem + 18432 + ((sel & 1) * 8 + rl) * 272
                         + (nOff + (sel >> 1) * 8) * 2;

    float d[4][4][4];
    #pragma unroll
    for (int f = 0; f < 4; ++f)
        #pragma unroll
        for (int g = 0; g < 4; ++g)
            #pragma unroll
            for (int j = 0; j < 4; ++j) d[f][g][j] = 0.f;

    auto issue = [&](int ch, uint32_t soff) {
        const int k0 = ch * 64;
        #pragma unroll
        for (int it = 0; it < 4; ++it)
            cp_async16(aDst[it] + soff, aSrc[it] + k0);
        #pragma unroll
        for (int it = 0; it < 4; ++it)
            cp_async16(bDst[it] + soff, bSrc[it] + (size_t)k0 * 1024);
        cp_commit();
    };

    issue(0, 0);
    issue(1, DN_STG);

    uint32_t cs = 0, ns = 2 * DN_STG;
    for (int ch = 0; ch < 16; ++ch) {
        if (ch < 15) cp_wait<1>(); else cp_wait<0>();
        __syncthreads();
        if (ch < 14) {
            issue(ch + 2, ns);
            ns = (ns == 2 * DN_STG) ? 0 : ns + DN_STG;
        }
        #pragma unroll
        for (int ks = 0; ks < 4; ++ks) {
            uint32_t af[4][4];
            #pragma unroll
            for (int f = 0; f < 4; ++f)
                ldsm_x4(af[f], aBase + cs + f * 2304 + ks * 32);
            uint32_t bf[2][4];
            #pragma unroll
            for (int g2 = 0; g2 < 2; ++g2)
                ldsm_x4t(bf[g2], bBase + cs + ks * 4352 + g2 * 32);
            #pragma unroll
            for (int f = 0; f < 4; ++f)
                #pragma unroll
                for (int g = 0; g < 4; ++g)
                    mma_f16(d[f][g], af[f], &bf[g >> 1][(g & 1) * 2]);
        }
        cs = (cs == 2 * DN_STG) ? 0 : cs + DN_STG;
    }

    #pragma unroll
    for (int f = 0; f < 4; ++f) {
        const int r = mBase + wm * 64 + f * 16 + row4;
        #pragma unroll
        for (int g = 0; g < 4; ++g) {
            const int c = nBase + nOff + g * 8 + kq * 2;
            *(__half2*)(Out + (size_t)r * 1024 + c) =
                __floats2half2_rn(d[f][g][0], d[f][g][1]);
            *(__half2*)(Out + (size_t)(r + 8) * 1024 + c) =
                __floats2half2_rn(d[f][g][2], d[f][g][3]);
        }
    }
}

// =============================================================================
// Final combine: out[t] = w0*Y[inv[2t]] + w1*Y[inv[2t+1]] + g_gate[t]*S[t]
// =============================================================================
__global__ void __launch_bounds__(256) combine_kernel(
    const float* __restrict__ tw, float* __restrict__ out)
{
    const int t = blockIdx.x;
    const int tid = threadIdx.x;

    const float g = g_gate[t];
    const int r0 = g_inv[2 * t], r1 = g_inv[2 * t + 1];
    const float w0 = tw[2 * t], w1 = tw[2 * t + 1];

    const __half2* y0 = (const __half2*)(g_Y + (size_t)r0 * 1024) + 2 * tid;
    const __half2* y1 = (const __half2*)(g_Y + (size_t)r1 * 1024) + 2 * tid;
    const __half2* sv = (const __half2*)(g_S + (size_t)t  * 1024) + 2 * tid;
    const float2 a0 = __half22float2(y0[0]), a1 = __half22float2(y0[1]);
    const float2 b0 = __half22float2(y1[0]), b1 = __half22float2(y1[1]);
    const float2 c0 = __half22float2(sv[0]), c1 = __half22float2(sv[1]);
    float4 r;
    r.x = w0 * a0.x + w1 * b0.x + g * c0.x;
    r.y = w0 * a0.y + w1 * b0.y + g * c0.y;
    r.z = w0 * a1.x + w1 * b1.x + g * c1.x;
    r.w = w0 * a1.y + w1 * b1.y + g * c1.y;
    ((float4*)(out + (size_t)t * 1024))[tid] = r;
}

// =============================================================================
extern "C" void kernel_launch(void* const* d_in, const int* in_sizes, int n_in,
                              void* d_out, int out_size) {
    (void)in_sizes; (void)n_in; (void)out_size;
    const float* X   = (const float*)d_in[0];
    const float* tw  = (const float*)d_in[1];
    const float* wg  = (const float*)d_in[2];
    const float* wu  = (const float*)d_in[3];
    const float* wd  = (const float*)d_in[4];
    const float* swg = (const float*)d_in[5];
    const float* swu = (const float*)d_in[6];
    const float* swd = (const float*)d_in[7];
    const float* gw  = (const float*)d_in[8];
    const int*   tki = (const int*)d_in[9];
    float* out = (float*)d_out;

    __half *hX, *hWg, *hWu, *hWd, *hSg, *hSu, *hSd, *H, *SH, *Y, *S;
    cudaGetSymbolAddress((void**)&hX,  g_hX);
    cudaGetSymbolAddress((void**)&hWg, g_hwg);
    cudaGetSymbolAddress((void**)&hWu, g_hwu);
    cudaGetSymbolAddress((void**)&hWd, g_hwd);
    cudaGetSymbolAddress((void**)&hSg, g_hswg);
    cudaGetSymbolAddress((void**)&hSu, g_hswu);
    cudaGetSymbolAddress((void**)&hSd, g_hswd);
    cudaGetSymbolAddress((void**)&H,   g_H);
    cudaGetSymbolAddress((void**)&SH,  g_SH);
    cudaGetSymbolAddress((void**)&Y,   g_Y);
    cudaGetSymbolAddress((void**)&S,   g_S);

    // one-time (uncaptured first call) stream/event creation — no device allocs
    static cudaStream_t s1 = nullptr, s2 = nullptr;
    static cudaEvent_t evStart = nullptr, evCvtS = nullptr, evCvtR = nullptr,
                       evCvtB = nullptr, evPerm = nullptr, evShared = nullptr,
                       evGate = nullptr;
    if (!s1) {
        cudaStreamCreateWithFlags(&s1, cudaStreamNonBlocking);
        cudaStreamCreateWithFlags(&s2, cudaStreamNonBlocking);
        cudaEventCreateWithFlags(&evStart,  cudaEventDisableTiming);
        cudaEventCreateWithFlags(&evCvtS,   cudaEventDisableTiming);
        cudaEventCreateWithFlags(&evCvtR,   cudaEventDisableTiming);
        cudaEventCreateWithFlags(&evCvtB,   cudaEventDisableTiming);
        cudaEventCreateWithFlags(&evPerm,   cudaEventDisableTiming);
        cudaEventCreateWithFlags(&evShared, cudaEventDisableTiming);
        cudaEventCreateWithFlags(&evGate,   cudaEventDisableTiming);
        cudaFuncSetAttribute(gemm_gu<true >, cudaFuncAttributeMaxDynamicSharedMemorySize, GU_SMEM);
        cudaFuncSetAttribute(gemm_gu<false>, cudaFuncAttributeMaxDynamicSharedMemorySize, GU_SMEM);
        cudaFuncSetAttribute(gemm_dn,        cudaFuncAttributeMaxDynamicSharedMemorySize, DN_SMEM);
    }

    // ---- stream 0: cvtS (shared-GU gate), cvtR (routed-GU gate) ----------------
    cudaEventRecord(evStart, 0);
    cvt_S<<<1184, 256>>>(X, swg, swu);
    cudaEventRecord(evCvtS, 0);
    cvt_R<<<2368, 256>>>(wg, wu);
    cudaEventRecord(evCvtR, 0);

    // ---- stream s2: perm + gate (|| cvt), then cvtB under the GU phase ---------
    cudaStreamWaitEvent(s2, evStart, 0);
    build_perm_kernel<<<NEXP, 256, 0, s2>>>(tki);
    cudaEventRecord(evPerm, s2);
    gate_kernel<<<512, 256, 0, s2>>>(X, gw);
    cudaEventRecord(evGate, s2);
    cudaStreamWaitEvent(s2, evCvtR, 0);
    cvt_B<<<592, 256, 0, s2>>>(wd, swd);
    cudaEventRecord(evCvtB, s2);

    // ---- stream s1: shared chain (starts as soon as cvtS lands) ----------------
    cudaStreamWaitEvent(s1, evCvtS, 0);
    gemm_gu<false><<<dim3(32, 16, 1), 256, GU_SMEM, s1>>>(hX, hSg, hSu, SH);
    cudaStreamWaitEvent(s1, evCvtB, 0);
    gemm_dn<<<dim3(32, 8, 1), 256, DN_SMEM, s1>>>(SH, hSd, S);
    cudaEventRecord(evShared, s1);

    // ---- stream 0: routed chain, then join + combine ---------------------------
    cudaStreamWaitEvent(0, evPerm, 0);
    gemm_gu<true ><<<dim3(8, 16, NEXP), 256, GU_SMEM>>>(hX, hWg, hWu, H);
    cudaStreamWaitEvent(0, evCvtB, 0);
    gemm_dn<<<dim3(8, 8, NEXP), 256, DN_SMEM>>>(H, hWd, Y);
    cudaStreamWaitEvent(0, evShared, 0);
    cudaStreamWaitEvent(0, evGate, 0);
    combine_kernel<<<NTOK, 256>>>(tw, out);
}

// round 14
// speedup vs baseline: 1.0400x; 1.0172x over previous
#include <cuda_runtime.h>
#include <cuda_fp16.h>
#include <cstdint>

// =============================================================================
// MoE fused layer, plain sm_103. R14: GEMMs byte-identical to R11-R13.
// Head re-sequenced: cvtS runs with exclusive DRAM bandwidth (perm/gate/cvtR
// concurrency deferred past evCvtS); perm widened to 1024 threads.
// T=4096, D=1024, E=8, K=2, F=SF=1024.
// =============================================================================

#define NEXP   8
#define NTOK   4096
#define NROWS  8192
#define CPE    1024

// ---------------- device-global scratch --------------------------------------
__device__ __align__(16) __half g_hX  [4096u * 1024u];
__device__ __align__(16) __half g_hwg [8u * 1024u * 1024u];
__device__ __align__(16) __half g_hwu [8u * 1024u * 1024u];
__device__ __align__(16) __half g_hwd [8u * 1024u * 1024u];
__device__ __align__(16) __half g_hswg[1024u * 1024u];
__device__ __align__(16) __half g_hswu[1024u * 1024u];
__device__ __align__(16) __half g_hswd[1024u * 1024u];
__device__ __align__(16) __half g_H [8192u * 1024u];   // routed hidden
__device__ __align__(16) __half g_SH[4096u * 1024u];   // shared hidden
__device__ __align__(16) __half g_Y [8192u * 1024u];   // routed down out (fp16)
__device__ __align__(16) __half g_S [4096u * 1024u];   // shared down out (fp16)
__device__ float g_gate[4096];                          // sigmoid(X . gw)
__device__ int   g_perm[8192];
__device__ int   g_inv [8192];

// ---------------- helpers ------------------------------------------------------
__device__ __forceinline__ uint32_t smem_u32(const void* p) {
    uint32_t a;
    asm("{ .reg .u64 t; cvta.to.shared.u64 t, %1; cvt.u32.u64 %0, t; }"
        : "=r"(a) : "l"(p));
    return a;
}
__device__ __forceinline__ void cp_async16(uint32_t dst, const void* src) {
    asm volatile("cp.async.cg.shared.global [%0], [%1], 16;"
                 :: "r"(dst), "l"(src) : "memory");
}
__device__ __forceinline__ void cp_commit() {
    asm volatile("cp.async.commit_group;" ::: "memory");
}
template<int N>
__device__ __forceinline__ void cp_wait() {
    asm volatile("cp.async.wait_group %0;" :: "n"(N) : "memory");
}
__device__ __forceinline__ void ldsm_x4(uint32_t* r, uint32_t addr) {
    asm volatile("ldmatrix.sync.aligned.m8n8.x4.shared.b16 {%0,%1,%2,%3}, [%4];"
                 : "=r"(r[0]), "=r"(r[1]), "=r"(r[2]), "=r"(r[3]) : "r"(addr));
}
__device__ __forceinline__ void ldsm_x4t(uint32_t* r, uint32_t addr) {
    asm volatile("ldmatrix.sync.aligned.m8n8.x4.trans.shared.b16 {%0,%1,%2,%3}, [%4];"
                 : "=r"(r[0]), "=r"(r[1]), "=r"(r[2]), "=r"(r[3]) : "r"(addr));
}
__device__ __forceinline__ void mma_f16(float* d, const uint32_t* a,
                                        const uint32_t* b) {
    asm volatile(
        "mma.sync.aligned.m16n8k16.row.col.f32.f16.f16.f32 "
        "{%0,%1,%2,%3}, {%4,%5,%6,%7}, {%8,%9}, {%0,%1,%2,%3};"
        : "+f"(d[0]), "+f"(d[1]), "+f"(d[2]), "+f"(d[3])
        : "r"(a[0]), "r"(a[1]), "r"(a[2]), "r"(a[3]), "r"(b[0]), "r"(b[1]));
}
__device__ __forceinline__ float silu(float x) {
    return x / (1.f + __expf(-x));
}

// =============================================================================
// cvtS: X(1048576) swg(262144) swu(262144) = 1572864 f4 (gates shared GU).
// cvtR: wg(2097152) wu(2097152) = 4194304 f4 (gates routed GU).
// cvtB: wd(2097152) swd(262144) = 2359296 f4 (gates the DNs).
// =============================================================================
__global__ void __launch_bounds__(256) cvt_S(
    const float* __restrict__ x,
    const float* __restrict__ swg, const float* __restrict__ swu)
{
    const size_t total = 1572864u;
    for (size_t i = (size_t)blockIdx.x * blockDim.x + threadIdx.x;
         i < total; i += (size_t)gridDim.x * blockDim.x) {
        const float4* s; __half2* d; size_t j;
        if      (i < 1048576u) { s = (const float4*)x;   d = (__half2*)g_hX;   j = i; }
        else if (i < 1310720u) { s = (const float4*)swg; d = (__half2*)g_hswg; j = i - 1048576u; }
        else                   { s = (const float4*)swu; d = (__half2*)g_hswu; j = i - 1310720u; }
        const float4 v = s[j];
        d[2 * j]     = __floats2half2_rn(v.x, v.y);
        d[2 * j + 1] = __floats2half2_rn(v.z, v.w);
    }
}

__global__ void __launch_bounds__(256) cvt_R(
    const float* __restrict__ wg, const float* __restrict__ wu)
{
    const size_t total = 4194304u;
    for (size_t i = (size_t)blockIdx.x * blockDim.x + threadIdx.x;
         i < total; i += (size_t)gridDim.x * blockDim.x) {
        const float4* s; __half2* d; size_t j;
        if (i < 2097152u) { s = (const float4*)wg; d = (__half2*)g_hwg; j = i; }
        else              { s = (const float4*)wu; d = (__half2*)g_hwu; j = i - 2097152u; }
        const float4 v = s[j];
        d[2 * j]     = __floats2half2_rn(v.x, v.y);
        d[2 * j + 1] = __floats2half2_rn(v.z, v.w);
    }
}

__global__ void __launch_bounds__(256) cvt_B(
    const float* __restrict__ wd, const float* __restrict__ swd)
{
    const size_t total = 2359296u;
    for (size_t i = (size_t)blockIdx.x * blockDim.x + threadIdx.x;
         i < total; i += (size_t)gridDim.x * blockDim.x) {
        const float4* s; __half2* d; size_t j;
        if (i < 2097152u) { s = (const float4*)wd;  d = (__half2*)g_hwd;  j = i; }
        else              { s = (const float4*)swd; d = (__half2*)g_hswd; j = i - 2097152u; }
        const float4 v = s[j];
        d[2 * j]     = __floats2half2_rn(v.x, v.y);
        d[2 * j + 1] = __floats2half2_rn(v.z, v.w);
    }
}

// =============================================================================
// Shared-expert sigmoid gate: g_gate[t] = sigmoid(X[t] . gw). Warp per token.
// =============================================================================
__global__ void __launch_bounds__(256) gate_kernel(
    const float* __restrict__ X, const float* __restrict__ gw)
{
    const int w    = threadIdx.x >> 5;
    const int lane = threadIdx.x & 31;
    const int t    = blockIdx.x * 8 + w;
    const float4* xr = (const float4*)(X + (size_t)t * 1024);
    const float4* gr = (const float4*)gw;
    float acc = 0.f;
    #pragma unroll
    for (int i = 0; i < 8; ++i) {
        const float4 a = xr[lane + i * 32];
        const float4 b = gr[lane + i * 32];
        acc += a.x * b.x + a.y * b.y + a.z * b.z + a.w * b.w;
    }
    #pragma unroll
    for (int o = 16; o; o >>= 1)
        acc += __shfl_xor_sync(0xffffffffu, acc, o);
    if (lane == 0)
        g_gate[t] = 1.f / (1.f + __expf(-acc));
}

// =============================================================================
// Stable counting-sort permutation via warp ballots. 1024 threads/expert:
// 8 chunk iterations instead of 32.
// =============================================================================
__global__ void __launch_bounds__(1024) build_perm_kernel(
    const int* __restrict__ tki)
{
    const int e    = blockIdx.x;
    const int tid  = threadIdx.x;
    const int lane = tid & 31;
    const int w    = tid >> 5;            // 0..31
    __shared__ int wcnt[32];
    __shared__ int basev;
    if (tid == 0) basev = 0;
    __syncthreads();
    for (int start = 0; start < NROWS; start += 1024) {
        const int i = start + tid;
        const bool m = (tki[i] == e);
        const uint32_t mask = __ballot_sync(0xffffffffu, m);
        if (lane == 0) wcnt[w] = __popc(mask);
        __syncthreads();
        int wpre = 0, tot = 0;
        #pragma unroll
        for (int ww = 0; ww < 32; ++ww) {
            const int c = wcnt[ww];
            wpre += (ww < w) ? c : 0;
            tot  += c;
        }
        if (m) {
            const int rank = __popc(mask & ((1u << lane) - 1u));
            const int dest = e * CPE + basev + wpre + rank;
            g_perm[dest] = i;
            g_inv[i] = dest;
        }
        __syncthreads();
        if (tid == 0) basev += tot;
        __syncthreads();
    }
}

// =============================================================================
// Fused gate+up GEMM (R8 verbatim — ceiling-bound, do not touch).
// =============================================================================
#define GU_STG   36864
#define GU_SMEM  (3 * GU_STG + 512)

template<bool GATHER>
__global__ void __launch_bounds__(256, 2) gemm_gu(
    const __half* __restrict__ A,
    const __half* __restrict__ B0g,
    const __half* __restrict__ B1g,
    __half* __restrict__ Out)
{
    extern __shared__ char sm[];
    const uint32_t smem = smem_u32(sm);
    int* srcRow = (int*)(sm + 3 * GU_STG);

    const int tid  = threadIdx.x;
    const int wid  = tid >> 5;
    const int lane = tid & 31;
    const int row4 = lane >> 2;
    const int kq   = lane & 3;
    const int rl   = lane & 7;
    const int sel  = lane >> 3;
    const int mat  = wid >> 2;
    const int wm   = (wid >> 1) & 1;
    const int wn2  = wid & 1;

    const int mBase = (blockIdx.z * gridDim.x + blockIdx.x) * 128;
    const int nBase = blockIdx.y * 64;

    if (tid < 128)
        srcRow[tid] = GATHER ? (g_perm[mBase + tid] >> 1) : (mBase + tid);
    __syncthreads();

    const __half* B0 = B0g + (size_t)blockIdx.z * 1048576u;
    const __half* B1 = B1g + (size_t)blockIdx.z * 1048576u;

    const __half* aSrc[4]; uint32_t aDst[4];
    const __half* bSrc[4]; uint32_t bDst[4];
    #pragma unroll
    for (int it = 0; it < 4; ++it) {
        const int ia = tid + it * 256;
        const int r = ia >> 3, q = ia & 7;
        aSrc[it] = A + (size_t)srcRow[r] * 1024 + q * 8;
        aDst[it] = smem + r * 144 + q * 16;
        const int mm = ia >> 9, kr = (ia >> 3) & 63, qb = ia & 7;
        bSrc[it] = (mm ? B1 : B0) + (size_t)kr * 1024 + nBase + qb * 8;
        bDst[it] = smem + 18432 + mm * 9216 + kr * 144 + qb * 16;
    }

    const uint32_t aBase = smem + (wm * 64 + (sel & 1) * 8 + rl) * 144
                         + (sel >> 1) * 16;
    const uint32_t bBase = smem + 18432 + mat * 9216
                         + ((sel & 1) * 8 + rl) * 144
                         + (wn2 * 32 + (sel >> 1) * 8) * 2;

    float d[4][4][4];
    #pragma unroll
    for (int f = 0; f < 4; ++f)
        #pragma unroll
        for (int g = 0; g < 4; ++g)
            #pragma unroll
            for (int j = 0; j < 4; ++j) d[f][g][j] = 0.f;

    auto issue = [&](int ch, uint32_t soff) {
        const int k0 = ch * 64;
        #pragma unroll
        for (int it = 0; it < 4; ++it)
            cp_async16(aDst[it] + soff, aSrc[it] + k0);
        #pragma unroll
        for (int it = 0; it < 4; ++it)
            cp_async16(bDst[it] + soff, bSrc[it] + (size_t)k0 * 1024);
        cp_commit();
    };

    issue(0, 0);
    issue(1, GU_STG);

    uint32_t cs = 0, ns = 2 * GU_STG;
    for (int ch = 0; ch < 16; ++ch) {
        if (ch < 15) cp_wait<1>(); else cp_wait<0>();
        __syncthreads();
        if (ch < 14) {
            issue(ch + 2, ns);
            ns = (ns == 2 * GU_STG) ? 0 : ns + GU_STG;
        }
        #pragma unroll
        for (int ks = 0; ks < 4; ++ks) {
            uint32_t af[4][4];
            #pragma unroll
            for (int f = 0; f < 4; ++f)
                ldsm_x4(af[f], aBase + cs + f * 2304 + ks * 32);
            uint32_t bf[2][4];
            #pragma unroll
            for (int g2 = 0; g2 < 2; ++g2)
                ldsm_x4t(bf[g2], bBase + cs + ks * 2304 + g2 * 32);
            #pragma unroll
            for (int f = 0; f < 4; ++f)
                #pragma unroll
                for (int g = 0; g < 4; ++g)
                    mma_f16(d[f][g], af[f], &bf[g >> 1][(g & 1) * 2]);
        }
        cs = (cs == 2 * GU_STG) ? 0 : cs + GU_STG;
    }

    __syncthreads();
    float* Us = (float*)sm;             // [128][66]
    if (mat == 1) {
        #pragma unroll
        for (int f = 0; f < 4; ++f) {
            const int r = wm * 64 + f * 16 + row4;
            #pragma unroll
            for (int g = 0; g < 4; ++g) {
                const int c = wn2 * 32 + g * 8 + kq * 2;
                *(float2*)(Us + r * 66 + c)       = make_float2(d[f][g][0], d[f][g][1]);
                *(float2*)(Us + (r + 8) * 66 + c) = make_float2(d[f][g][2], d[f][g][3]);
            }
        }
    }
    __syncthreads();
    if (mat == 0) {
        #pragma unroll
        for (int f = 0; f < 4; ++f) {
            const int r = wm * 64 + f * 16 + row4;
            #pragma unroll
            for (int g = 0; g < 4; ++g) {
                const int c = wn2 * 32 + g * 8 + kq * 2;
                const float2 u0 = *(const float2*)(Us + r * 66 + c);
                const float2 u1 = *(const float2*)(Us + (r + 8) * 66 + c);
                *(__half2*)(Out + (size_t)(mBase + r) * 1024 + nBase + c) =
                    __floats2half2_rn(silu(d[f][g][0]) * u0.x,
                                      silu(d[f][g][1]) * u0.y);
                *(__half2*)(Out + (size_t)(mBase + r + 8) * 1024 + nBase + c) =
                    __floats2half2_rn(silu(d[f][g][2]) * u1.x,
                                      silu(d[f][g][3]) * u1.y);
            }
        }
    }
}

// =============================================================================
// Down GEMM (R11 verbatim — fp16 out).
// =============================================================================
#define DN_STG   35840
#define DN_SMEM  (3 * DN_STG + 256)

__global__ void __launch_bounds__(256, 2) gemm_dn(
    const __half* __restrict__ A,
    const __half* __restrict__ Bg,
    __half* __restrict__ Out)
{
    extern __shared__ char sm[];
    const uint32_t smem = smem_u32(sm);

    const int tid  = threadIdx.x;
    const int wid  = tid >> 5;
    const int lane = tid & 31;
    const int row4 = lane >> 2;
    const int kq   = lane & 3;
    const int rl   = lane & 7;
    const int sel  = lane >> 3;
    const int wm   = wid & 1;
    const int nOff = (wid >> 1) * 32;

    const int mBase = (blockIdx.z * gridDim.x + blockIdx.x) * 128;
    const int nBase = blockIdx.y * 128;

    const __half* B = Bg + (size_t)blockIdx.z * (1024u * 1024u);

    const __half* aSrc[4]; uint32_t aDst[4];
    const __half* bSrc[4]; uint32_t bDst[4];
    #pragma unroll
    for (int it = 0; it < 4; ++it) {
        const int ia = tid + it * 256;
        const int r = ia >> 3, q = ia & 7;
        aSrc[it] = A + (size_t)(mBase + r) * 1024 + q * 8;
        aDst[it] = smem + r * 144 + q * 16;
        const int kr = ia >> 4, qb = ia & 15;
        bSrc[it] = B + (size_t)kr * 1024 + nBase + qb * 8;
        bDst[it] = smem + 18432 + kr * 272 + qb * 16;
    }

    const uint32_t aBase = smem + (wm * 64 + (sel & 1) * 8 + rl) * 144
                         + (sel >> 1) * 16;
    const uint32_t bBase = smem + 18432 + ((sel & 1) * 8 + rl) * 272
                         + (nOff + (sel >> 1) * 8) * 2;

    float d[4][4][4];
    #pragma unroll
    for (int f = 0; f < 4; ++f)
        #pragma unroll
        for (int g = 0; g < 4; ++g)
            #pragma unroll
            for (int j = 0; j < 4; ++j) d[f][g][j] = 0.f;

    auto issue = [&](int ch, uint32_t soff) {
        const int k0 = ch * 64;
        #pragma unroll
        for (int it = 0; it < 4; ++it)
            cp_async16(aDst[it] + soff, aSrc[it] + k0);
        #pragma unroll
        for (int it = 0; it < 4; ++it)
            cp_async16(bDst[it] + soff, bSrc[it] + (size_t)k0 * 1024);
        cp_commit();
    };

    issue(0, 0);
    issue(1, DN_STG);

    uint32_t cs = 0, ns = 2 * DN_STG;
    for (int ch = 0; ch < 16; ++ch) {
        if (ch < 15) cp_wait<1>(); else cp_wait<0>();
        __syncthreads();
        if (ch < 14) {
            issue(ch + 2, ns);
            ns = (ns == 2 * DN_STG) ? 0 : ns + DN_STG;
        }
        #pragma unroll
        for (int ks = 0; ks < 4; ++ks) {
            uint32_t af[4][4];
            #pragma unroll
            for (int f = 0; f < 4; ++f)
                ldsm_x4(af[f], aBase + cs + f * 2304 + ks * 32);
            uint32_t bf[2][4];
            #pragma unroll
            for (int g2 = 0; g2 < 2; ++g2)
                ldsm_x4t(bf[g2], bBase + cs + ks * 4352 + g2 * 32);
            #pragma unroll
            for (int f = 0; f < 4; ++f)
                #pragma unroll
                for (int g = 0; g < 4; ++g)
                    mma_f16(d[f][g], af[f], &bf[g >> 1][(g & 1) * 2]);
        }
        cs = (cs == 2 * DN_STG) ? 0 : cs + DN_STG;
    }

    #pragma unroll
    for (int f = 0; f < 4; ++f) {
        const int r = mBase + wm * 64 + f * 16 + row4;
        #pragma unroll
        for (int g = 0; g < 4; ++g) {
            const int c = nBase + nOff + g * 8 + kq * 2;
            *(__half2*)(Out + (size_t)r * 1024 + c) =
                __floats2half2_rn(d[f][g][0], d[f][g][1]);
            *(__half2*)(Out + (size_t)(r + 8) * 1024 + c) =
                __floats2half2_rn(d[f][g][2], d[f][g][3]);
        }
    }
}

// =============================================================================
// Final combine: out[t] = w0*Y[inv[2t]] + w1*Y[inv[2t+1]] + g_gate[t]*S[t]
// =============================================================================
__global__ void __launch_bounds__(256) combine_kernel(
    const float* __restrict__ tw, float* __restrict__ out)
{
    const int t = blockIdx.x;
    const int tid = threadIdx.x;

    const float g = g_gate[t];
    const int r0 = g_inv[2 * t], r1 = g_inv[2 * t + 1];
    const float w0 = tw[2 * t], w1 = tw[2 * t + 1];

    const __half2* y0 = (const __half2*)(g_Y + (size_t)r0 * 1024) + 2 * tid;
    const __half2* y1 = (const __half2*)(g_Y + (size_t)r1 * 1024) + 2 * tid;
    const __half2* sv = (const __half2*)(g_S + (size_t)t  * 1024) + 2 * tid;
    const float2 a0 = __half22float2(y0[0]), a1 = __half22float2(y0[1]);
    const float2 b0 = __half22float2(y1[0]), b1 = __half22float2(y1[1]);
    const float2 c0 = __half22float2(sv[0]), c1 = __half22float2(sv[1]);
    float4 r;
    r.x = w0 * a0.x + w1 * b0.x + g * c0.x;
    r.y = w0 * a0.y + w1 * b0.y + g * c0.y;
    r.z = w0 * a1.x + w1 * b1.x + g * c1.x;
    r.w = w0 * a1.y + w1 * b1.y + g * c1.y;
    ((float4*)(out + (size_t)t * 1024))[tid] = r;
}

// =============================================================================
extern "C" void kernel_launch(void* const* d_in, const int* in_sizes, int n_in,
                              void* d_out, int out_size) {
    (void)in_sizes; (void)n_in; (void)out_size;
    const float* X   = (const float*)d_in[0];
    const float* tw  = (const float*)d_in[1];
    const float* wg  = (const float*)d_in[2];
    const float* wu  = (const float*)d_in[3];
    const float* wd  = (const float*)d_in[4];
    const float* swg = (const float*)d_in[5];
    const float* swu = (const float*)d_in[6];
    const float* swd = (const float*)d_in[7];
    const float* gw  = (const float*)d_in[8];
    const int*   tki = (const int*)d_in[9];
    float* out = (float*)d_out;

    __half *hX, *hWg, *hWu, *hWd, *hSg, *hSu, *hSd, *H, *SH, *Y, *S;
    cudaGetSymbolAddress((void**)&hX,  g_hX);
    cudaGetSymbolAddress((void**)&hWg, g_hwg);
    cudaGetSymbolAddress((void**)&hWu, g_hwu);
    cudaGetSymbolAddress((void**)&hWd, g_hwd);
    cudaGetSymbolAddress((void**)&hSg, g_hswg);
    cudaGetSymbolAddress((void**)&hSu, g_hswu);
    cudaGetSymbolAddress((void**)&hSd, g_hswd);
    cudaGetSymbolAddress((void**)&H,   g_H);
    cudaGetSymbolAddress((void**)&SH,  g_SH);
    cudaGetSymbolAddress((void**)&Y,   g_Y);
    cudaGetSymbolAddress((void**)&S,   g_S);

    // one-time (uncaptured first call) stream/event creation — no device allocs
    static cudaStream_t s1 = nullptr, s2 = nullptr;
    static cudaEvent_t evCvtS = nullptr, evCvtR = nullptr, evCvtB = nullptr,
                       evPerm = nullptr, evShared = nullptr, evGate = nullptr;
    if (!s1) {
        cudaStreamCreateWithFlags(&s1, cudaStreamNonBlocking);
        cudaStreamCreateWithFlags(&s2, cudaStreamNonBlocking);
        cudaEventCreateWithFlags(&evCvtS,   cudaEventDisableTiming);
        cudaEventCreateWithFlags(&evCvtR,   cudaEventDisableTiming);
        cudaEventCreateWithFlags(&evCvtB,   cudaEventDisableTiming);
        cudaEventCreateWithFlags(&evPerm,   cudaEventDisableTiming);
        cudaEventCreateWithFlags(&evShared, cudaEventDisableTiming);
        cudaEventCreateWithFlags(&evGate,   cudaEventDisableTiming);
        cudaFuncSetAttribute(gemm_gu<true >, cudaFuncAttributeMaxDynamicSharedMemorySize, GU_SMEM);
        cudaFuncSetAttribute(gemm_gu<false>, cudaFuncAttributeMaxDynamicSharedMemorySize, GU_SMEM);
        cudaFuncSetAttribute(gemm_dn,        cudaFuncAttributeMaxDynamicSharedMemorySize, DN_SMEM);
    }

    // ---- stream 0: cvtS ALONE first (exclusive bandwidth), then cvtR ----------
    cvt_S<<<1184, 256>>>(X, swg, swu);
    cudaEventRecord(evCvtS, 0);
    cvt_R<<<2368, 256>>>(wg, wu);
    cudaEventRecord(evCvtR, 0);

    // ---- stream s2: perm + gate AFTER cvtS, then cvtB under the GU phase -------
    cudaStreamWaitEvent(s2, evCvtS, 0);
    build_perm_kernel<<<NEXP, 1024, 0, s2>>>(tki);
    cudaEventRecord(evPerm, s2);
    gate_kernel<<<512, 256, 0, s2>>>(X, gw);
    cudaEventRecord(evGate, s2);
    cudaStreamWaitEvent(s2, evCvtR, 0);
    cvt_B<<<592, 256, 0, s2>>>(wd, swd);
    cudaEventRecord(evCvtB, s2);

    // ---- stream s1: shared chain (starts as soon as cvtS lands) ----------------
    cudaStreamWaitEvent(s1, evCvtS, 0);
    gemm_gu<false><<<dim3(32, 16, 1), 256, GU_SMEM, s1>>>(hX, hSg, hSu, SH);
    cudaStreamWaitEvent(s1, evCvtB, 0);
    gemm_dn<<<dim3(32, 8, 1), 256, DN_SMEM, s1>>>(SH, hSd, S);
    cudaEventRecord(evShared, s1);

    // ---- stream 0: routed chain, then join + combine ---------------------------
    cudaStreamWaitEvent(0, evPerm, 0);
    gemm_gu<true ><<<dim3(8, 16, NEXP), 256, GU_SMEM>>>(hX, hWg, hWu, H);
    cudaStreamWaitEvent(0, evCvtB, 0);
    gemm_dn<<<dim3(8, 8, NEXP), 256, DN_SMEM>>>(H, hWd, Y);
    cudaStreamWaitEvent(0, evShared, 0);
    cudaStreamWaitEvent(0, evGate, 0);
    combine_kernel<<<NTOK, 256>>>(tw, out);
}